// round 11
// baseline (speedup 1.0000x reference)
#include <cuda_runtime.h>
#include <cuda_fp16.h>
#include <cstdint>

#define EMB    1024
#define HID    128
#define PW     64
#define KSEG   2112          // W1 rows [1024,3136): bm(1024) + sim(1024) + pw(64)
#define NCHUNK 34            // 32 e-chunks (K=32, sim folded into B) + 2 pw chunks
#define EPSV   1e-7f

// -------------------- device scratch (no allocs allowed) --------------------
__device__ __half g_allm_h[10016 * EMB];   // fp16 all_mentions, plain layout
__device__ __half g_W1Th[HID * KSEG];      // fp16 W1^T, per-32-chunk fragment-permuted
__device__ __half g_amb_hp[512 * EMB];     // fp16 mentions_batch, fragment-permuted
__device__ __half g_pw_h[512 * 64 * PW];   // fp16 pw, plain
__device__ int    g_idx64;

// fragment permutation within a 32-k chunk (matches m16n8k16 B/mult layout):
// t=(k>>1)&3, hi=(k>>3)&1, b=k&1, h16=k>>4  ->  pos = t*8 + h16*4 + hi*2 + b
__device__ __forceinline__ int permk(int kk) {
    return ((kk >> 1) & 3) * 8 + (kk >> 4) * 4 + ((kk >> 3) & 1) * 2 + (kk & 1);
}

// -------------------- helpers --------------------
__device__ __forceinline__ uint32_t smem_u32(const void* p) {
    uint32_t a;
    asm("{ .reg .u64 t; cvta.to.shared.u64 t, %1; cvt.u32.u64 %0, t; }" : "=r"(a) : "l"(p));
    return a;
}
__device__ __forceinline__ unsigned long long to_global(const void* p) {
    unsigned long long g;
    asm("cvta.to.global.u64 %0, %1;" : "=l"(g) : "l"(p));
    return g;
}
#define CP16(dst_s32, src_g64) \
    asm volatile("cp.async.cg.shared.global [%0], [%1], 16;" :: "r"(dst_s32), "l"(src_g64) : "memory")
#define CP_COMMIT() asm volatile("cp.async.commit_group;" ::: "memory")
#define CP_WAIT2()  asm volatile("cp.async.wait_group 2;" ::: "memory")

__device__ __forceinline__ void mma_f16(float c[4], uint32_t a0, uint32_t a1, uint32_t a2, uint32_t a3,
                                        uint32_t b0, uint32_t b1) {
    asm volatile("mma.sync.aligned.m16n8k16.row.col.f32.f16.f16.f32 "
                 "{%0,%1,%2,%3}, {%4,%5,%6,%7}, {%8,%9}, {%0,%1,%2,%3};"
                 : "+f"(c[0]), "+f"(c[1]), "+f"(c[2]), "+f"(c[3])
                 : "r"(a0), "r"(a1), "r"(a2), "r"(a3), "r"(b0), "r"(b1));
}
#define LDSM_X4(r0, r1, r2, r3, addr) \
    asm volatile("ldmatrix.sync.aligned.m8n8.x4.shared.b16 {%0,%1,%2,%3}, [%4];" \
                 : "=r"(r0), "=r"(r1), "=r"(r2), "=r"(r3) : "r"(addr))

__device__ __forceinline__ uint32_t hfma2u(uint32_t a, uint32_t b, uint32_t c) {
    uint32_t d;
    asm("fma.rn.f16x2 %0, %1, %2, %3;" : "=r"(d) : "r"(a), "r"(b), "r"(c));
    return d;
}
__device__ __forceinline__ int load_idx(const void* p, size_t pos, int is64) {
    return is64 ? (int)((const long long*)p)[pos] : ((const int*)p)[pos];
}

// -------------------- single prep kernel: fp16 conversions + permutes + idx detect ------------
__global__ __launch_bounds__(256)
void prep_kernel(const float* __restrict__ all_m, const float* __restrict__ m_b,
                 const float* __restrict__ pw, const float* __restrict__ W1,
                 const unsigned* __restrict__ idxw, int n_words,
                 int n_mentions, int batch, int n_ants) {
    if (blockIdx.x == 0 && threadIdx.x == 0) {
        unsigned acc = 0;
        int m = n_words < 256 ? n_words : 256;
        for (int i = 1; i < m; i += 2) acc |= idxw[i];
        g_idx64 = (acc == 0u) ? 1 : 0;
    }
    const long long n4a = (long long)n_mentions * EMB / 4;
    const long long nw1 = (long long)KSEG * HID;
    const long long nmb = (long long)batch * EMB;
    const long long npw = (long long)batch * n_ants * PW;
    const long long TOT = n4a + nw1 + nmb + npw;
    const long long stride = (long long)gridDim.x * blockDim.x;
    for (long long i = (long long)blockIdx.x * blockDim.x + threadIdx.x; i < TOT; i += stride) {
        if (i < n4a) {
            float4 v = ((const float4*)all_m)[i];
            __half2* d = (__half2*)(g_allm_h + i * 4);
            d[0] = __floats2half2_rn(v.x, v.y);
            d[1] = __floats2half2_rn(v.z, v.w);
        } else if (i < n4a + nw1) {
            long long j = i - n4a;
            int k = (int)(j / HID), n = (int)(j % HID);
            float v = W1[(size_t)(1024 + k) * HID + n];
            g_W1Th[(size_t)n * KSEG + (k & ~31) + permk(k & 31)] = __float2half_rn(v);
        } else if (i < n4a + nw1 + nmb) {
            long long j = i - n4a - nw1;
            int b = (int)(j >> 10), k = (int)(j & 1023);
            g_amb_hp[(size_t)b * EMB + (k & ~31) + permk(k & 31)] = __float2half_rn(m_b[j]);
        } else {
            long long j = i - n4a - nw1 - nmb;
            g_pw_h[j] = __float2half_rn(pw[j]);
        }
    }
}

// -------------------- fused fp16 pair kernel --------------------
// Block: 4 batch rows -> M=256, N=128, 512 threads / 16 warps, grid = batch/4 = 128.
// Warp (mi = wid&3, nh = wid>>2): rows [64mi,64mi+64), cols [32nh,32nh+32); bq == mi.
// A fragments via ldmatrix.x4 (plain layout, 80B pitch: LDSM conflict-free).
// B'' = WB + am (.) WS folded in registers (fp16).
// aproj: thread = (b, ngroup of 4, kshard of 4); 8 LDG.128 of W1 per chunk; fp32 exact.
#define OFF_IDX    0                     // 256 ints
#define OFF_WOUT   1024                  // 128 f
#define OFF_APROJ  1536                  // 512 f
#define OFF_MB     3584                  // 4 x 1024 f fp32 mentions_batch rows
#define OFF_STAGE  19968
#define ST_A       0                     // 256 rows x 80 B (32 halfs + pad)
#define ST_AM      20480                 // 4 x 64 B (permuted fp16)
#define ST_WB      20736                 // 128 x 64 B (permuted fp16)
#define ST_WS      28928                 // 128 x 64 B
#define STAGE_B    37120
#define SMEM_TOTAL (OFF_STAGE + 3 * STAGE_B)   // 131328

struct StageCtx {
    unsigned long long allm_g, w1t_g, pw_g, amb_g;
    int b0, n_ants;
};

__device__ __forceinline__ void stage_chunk(int c, uint32_t sbase,
                                            const int* idx_s, const StageCtx& cx, int tid) {
    const uint32_t stg = sbase + OFF_STAGE + (uint32_t)(c % 3) * STAGE_B;
    if (c < 32) {
        const int ec = c * 32;
#pragma unroll
        for (int it = 0; it < 2; it++) {       // A: gathered bm rows [256][32] fp16
            int id = tid + it * 512;
            int r = id >> 2, f4 = id & 3;
            unsigned long long src = cx.allm_g + ((size_t)idx_s[r] * EMB + ec) * 2ull + f4 * 16;
            CP16(stg + ST_A + (uint32_t)(r * 80 + f4 * 16), src);
        }
#pragma unroll
        for (int it = 0; it < 2; it++) {       // WB / WS (permuted fp16)
            int id = tid + it * 512;
            int seg = id >> 9, n = (id >> 2) & 127, f4 = id & 3;
            unsigned long long src = cx.w1t_g +
                ((size_t)n * KSEG + (seg ? 1024 + ec : ec)) * 2ull + f4 * 16;
            CP16(stg + (seg ? ST_WS : ST_WB) + (uint32_t)(n * 64 + f4 * 16), src);
        }
        if (tid < 16) {                        // AM: permuted am chunk [4][32] fp16
            int q = tid >> 2, f4 = tid & 3;
            unsigned long long src = cx.amb_g + ((size_t)(cx.b0 + q) * EMB + ec) * 2ull + f4 * 16;
            CP16(stg + ST_AM + (uint32_t)(q * 64 + f4 * 16), src);
        }
    } else {
        const int pc = (c - 32) * 32;
#pragma unroll
        for (int it = 0; it < 2; it++) {       // A: pw values [256][32] fp16
            int id = tid + it * 512;
            int r = id >> 2, f4 = id & 3;
            int bq = r >> 6, a = r & 63; if (a >= cx.n_ants) a = cx.n_ants - 1;
            unsigned long long src = cx.pw_g +
                (((size_t)(cx.b0 + bq) * cx.n_ants + a) * PW + pc) * 2ull + f4 * 16;
            CP16(stg + ST_A + (uint32_t)(r * 80 + f4 * 16), src);
        }
        {                                      // B: W1p (permuted) into WB region
            int n = tid >> 2, f4 = tid & 3;
            unsigned long long src = cx.w1t_g + ((size_t)n * KSEG + 2048 + pc) * 2ull + f4 * 16;
            CP16(stg + ST_WB + (uint32_t)(n * 64 + f4 * 16), src);
        }
    }
}

__global__ __launch_bounds__(512, 1)
void pair_mma_kernel(const float* __restrict__ m_b,
                     const void*  __restrict__ top_idx,
                     const float* __restrict__ rough,
                     const float* __restrict__ W1,
                     const float* __restrict__ b1,
                     const float* __restrict__ W_out,
                     const float* __restrict__ b_out,
                     float* __restrict__ out,
                     int n_ants) {
    extern __shared__ char smem[];
    const uint32_t sbase = smem_u32(smem);
    const int tid  = threadIdx.x;
    const int lane = tid & 31;
    const int wid  = tid >> 5;
    const int t    = lane & 3;       // k lane within quad
    const int q    = lane >> 2;      // row/col lane (0..7)
    const int b0   = blockIdx.x * 4;
    const int mi   = wid & 3;        // m-tile: rows [64mi,64mi+64); == bq
    const int nh   = wid >> 2;       // n-quarter: cols [32nh,32nh+32)
    const int rb   = mi * 64, nb = nh * 32;

    int*   idx_s   = (int*)(smem + OFF_IDX);
    float* wout_s  = (float*)(smem + OFF_WOUT);
    float* aproj_s = (float*)(smem + OFF_APROJ);
    float* mb_s    = (float*)(smem + OFF_MB);

    StageCtx cx;
    cx.allm_g = to_global(g_allm_h);
    cx.w1t_g  = to_global(g_W1Th);
    cx.pw_g   = to_global(g_pw_h);
    cx.amb_g  = to_global(g_amb_hp);
    cx.b0 = b0; cx.n_ants = n_ants;

    if (tid < 256) {
        int a = tid & 63; if (a >= n_ants) a = n_ants - 1;
        idx_s[tid] = load_idx(top_idx, (size_t)(b0 + (tid >> 6)) * n_ants + a, g_idx64);
    }
    if (tid < 128) wout_s[tid] = W_out[tid];
    {   // fp32 mentions_batch rows b0..b0+3 into smem (exact aproj inputs)
        const float4* src = (const float4*)(m_b + (size_t)b0 * EMB);
#pragma unroll
        for (int i2 = 0; i2 < 2; i2++) ((float4*)mb_s)[tid + i2 * 512] = src[tid + i2 * 512];
    }
    __syncthreads();

    stage_chunk(0, sbase, idx_s, cx, tid); CP_COMMIT();
    stage_chunk(1, sbase, idx_s, cx, tid); CP_COMMIT();
    stage_chunk(2, sbase, idx_s, cx, tid); CP_COMMIT();

    // accumulators: 4 m-frags x 4 n-frags x 4 (fp32)
    float acc[4][4][4];
#pragma unroll
    for (int i = 0; i < 4; i++)
#pragma unroll
        for (int nf = 0; nf < 4; nf++)
#pragma unroll
            for (int r = 0; r < 4; r++) acc[i][nf][r] = 0.f;

    // aproj: thread = (abq = tid>>7, ng = (tid>>2)&31, ks = tid&3); owns n = 4ng..4ng+3, k-shard ks
    const int abq = tid >> 7, ng = (tid >> 2) & 31, ks = tid & 3;
    float4 apacc = make_float4(0.f, 0.f, 0.f, 0.f);

    // ldmatrix lane base: row rb + (lane&15), k-half (lane>>4)
    const uint32_t a_lane_off = (uint32_t)((rb + (lane & 15)) * 80 + (lane >> 4) * 16);

    for (int c = 0; c < NCHUNK; c++) {
        CP_WAIT2();
        __syncthreads();                       // stage(c) ready

        const char* stp = smem + OFF_STAGE + (c % 3) * STAGE_B;
        const uint32_t stu = sbase + OFF_STAGE + (uint32_t)(c % 3) * STAGE_B;
        const bool has_sim = (c < 32);

        // B'' fold in registers: bpp[nf] = {b0s0, b1s0, b0s1, b1s1} half2s
        uint32_t bpp[4][4];
        {
            uint4 am4 = make_uint4(0, 0, 0, 0);
            if (has_sim) am4 = *(const uint4*)(stp + ST_AM + mi * 64 + t * 16);
#pragma unroll
            for (int nf = 0; nf < 4; nf++) {
                int n = nb + nf * 8 + q;
                uint4 wb = *(const uint4*)(stp + ST_WB + n * 64 + t * 16);
                if (has_sim) {
                    uint4 ws = *(const uint4*)(stp + ST_WS + n * 64 + t * 16);
                    bpp[nf][0] = hfma2u(am4.x, ws.x, wb.x);
                    bpp[nf][1] = hfma2u(am4.y, ws.y, wb.y);
                    bpp[nf][2] = hfma2u(am4.z, ws.z, wb.z);
                    bpp[nf][3] = hfma2u(am4.w, ws.w, wb.w);
                } else {
                    bpp[nf][0] = wb.x; bpp[nf][1] = wb.y;
                    bpp[nf][2] = wb.z; bpp[nf][3] = wb.w;
                }
            }
        }

#pragma unroll
        for (int s = 0; s < 2; s++) {          // two k16 steps
            uint32_t a_[4][4];
#pragma unroll
            for (int i = 0; i < 4; i++)
                LDSM_X4(a_[i][0], a_[i][1], a_[i][2], a_[i][3],
                        stu + a_lane_off + (uint32_t)(i * 16 * 80 + s * 32));
#pragma unroll
            for (int nf = 0; nf < 4; nf++) {
                uint32_t b0r = bpp[nf][2 * s], b1r = bpp[nf][2 * s + 1];
#pragma unroll
                for (int i = 0; i < 4; i++)
                    mma_f16(acc[i][nf], a_[i][0], a_[i][1], a_[i][2], a_[i][3], b0r, b1r);
            }
        }

        if (has_sim) {                          // aproj: 8 x (LDG.128 W1 + smem mb + 4 FMA)
            const int kbase = c * 32 + ks * 8;
            const float* mbr = mb_s + abq * EMB + kbase;
#pragma unroll
            for (int kk = 0; kk < 8; kk++) {
                float4 w4 = __ldg((const float4*)(W1 + (size_t)(kbase + kk) * HID) + ng);
                float m = mbr[kk];
                apacc.x += m * w4.x; apacc.y += m * w4.y;
                apacc.z += m * w4.z; apacc.w += m * w4.w;
            }
        }
        __syncthreads();                        // done reading stage(c)

        if (c + 3 < NCHUNK) stage_chunk(c + 3, sbase, idx_s, cx, tid);
        CP_COMMIT();
    }

    // ---- epilogue: reduce aproj k-shards, then scores ----
    float* part2 = (float*)(smem + OFF_STAGE);           // [512 outs][4 shards]
    part2[(abq * 128 + ng * 4 + 0) * 4 + ks] = apacc.x;
    part2[(abq * 128 + ng * 4 + 1) * 4 + ks] = apacc.y;
    part2[(abq * 128 + ng * 4 + 2) * 4 + ks] = apacc.z;
    part2[(abq * 128 + ng * 4 + 3) * 4 + ks] = apacc.w;
    __syncthreads();
    {
        int n = tid & 127;
        aproj_s[tid] = b1[n] + part2[tid * 4] + part2[tid * 4 + 1]
                             + part2[tid * 4 + 2] + part2[tid * 4 + 3];
    }
    __syncthreads();

    float* part = (float*)(smem + OFF_STAGE + 8192);     // [256][4] score partials
    const float  bo  = __ldg(b_out);
    const float* apq = aproj_s + mi * 128;
#pragma unroll
    for (int i = 0; i < 4; i++) {
        float s0 = 0.f, s1 = 0.f;               // rows rb+16i+q, rb+16i+q+8
#pragma unroll
        for (int nf = 0; nf < 4; nf++) {
            int n0 = nb + nf * 8 + 2 * t, n1 = n0 + 1;
            float w0 = wout_s[n0], w1 = wout_s[n1];
            float ap0 = apq[n0], ap1 = apq[n1];
            float h;
            h = acc[i][nf][0] + ap0; h = fmaxf(h, 0.f) + 0.01f * fminf(h, 0.f); s0 += h * w0;
            h = acc[i][nf][1] + ap1; h = fmaxf(h, 0.f) + 0.01f * fminf(h, 0.f); s0 += h * w1;
            h = acc[i][nf][2] + ap0; h = fmaxf(h, 0.f) + 0.01f * fminf(h, 0.f); s1 += h * w0;
            h = acc[i][nf][3] + ap1; h = fmaxf(h, 0.f) + 0.01f * fminf(h, 0.f); s1 += h * w1;
        }
        s0 += __shfl_xor_sync(0xffffffffu, s0, 1);
        s0 += __shfl_xor_sync(0xffffffffu, s0, 2);
        s1 += __shfl_xor_sync(0xffffffffu, s1, 1);
        s1 += __shfl_xor_sync(0xffffffffu, s1, 2);
        if (t == 0) {
            part[(rb + 16 * i + q) * 4 + nh]     = s0;
            part[(rb + 16 * i + q + 8) * 4 + nh] = s1;
        }
    }
    __syncthreads();

    if (tid < 256) {
        float sc = part[tid * 4] + part[tid * 4 + 1] + part[tid * 4 + 2] + part[tid * 4 + 3];
        int a = tid & 63, bg = b0 + (tid >> 6);
        if (a < n_ants)
            out[(size_t)bg * (n_ants + 1) + 1 + a] =
                rough[(size_t)bg * n_ants + a] + bo + sc;
        if (a == 0) out[(size_t)bg * (n_ants + 1)] = EPSV;
    }
}

// -------------------- launch --------------------
extern "C" void kernel_launch(void* const* d_in, const int* in_sizes, int n_in,
                              void* d_out, int out_size) {
    const float* all_m = (const float*)d_in[0];
    const float* m_b   = (const float*)d_in[1];
    const float* pw    = (const float*)d_in[2];
    const void*  idx   = d_in[3];
    const float* rough = (const float*)d_in[4];
    const float* W1    = (const float*)d_in[5];
    const float* b1    = (const float*)d_in[6];
    const float* Wo    = (const float*)d_in[7];
    const float* bo    = (const float*)d_in[8];
    float* out = (float*)d_out;

    const int n_mentions = in_sizes[0] / EMB;  // 10000
    const int batch      = in_sizes[1] / EMB;  // 512
    const int n_ants     = in_sizes[3] / batch;// 50

    cudaFuncSetAttribute(pair_mma_kernel,
                         cudaFuncAttributeMaxDynamicSharedMemorySize, SMEM_TOTAL);

    prep_kernel<<<1184, 256>>>(all_m, m_b, pw, W1, (const unsigned*)idx, in_sizes[3],
                               n_mentions, batch, n_ants);
    pair_mma_kernel<<<batch / 4, 512, SMEM_TOTAL>>>(m_b, idx, rough,
                                                    W1, b1, Wo, bo, out, n_ants);
}

// round 12
// speedup vs baseline: 1.0450x; 1.0450x over previous
#include <cuda_runtime.h>
#include <cuda_fp16.h>
#include <cstdint>

#define EMB    1024
#define HID    128
#define PW     64
#define KSEG   2112          // W1 rows [1024,3136): bm(1024) + sim(1024) + pw(64)
#define NCHUNK 34            // 32 e-chunks (K=32, sim folded into B) + 2 pw chunks
#define EPSV   1e-7f

// -------------------- device scratch (no allocs allowed) --------------------
__device__ __half g_allm_h[10016 * EMB];   // fp16 all_mentions, plain layout
__device__ __half g_W1Th[HID * KSEG];      // fp16 W1^T, per-32-chunk fragment-permuted
__device__ __half g_amb_hp[512 * EMB];     // fp16 mentions_batch, fragment-permuted
__device__ __half g_pw_h[512 * 64 * PW];   // fp16 pw, plain
__device__ int    g_idx64;

// fragment permutation within a 32-k chunk (matches m16n8k16 B/mult layout):
// t=(k>>1)&3, hi=(k>>3)&1, b=k&1, h16=k>>4  ->  pos = t*8 + h16*4 + hi*2 + b
__device__ __forceinline__ int permk(int kk) {
    return ((kk >> 1) & 3) * 8 + (kk >> 4) * 4 + ((kk >> 3) & 1) * 2 + (kk & 1);
}

// -------------------- helpers --------------------
__device__ __forceinline__ uint32_t smem_u32(const void* p) {
    uint32_t a;
    asm("{ .reg .u64 t; cvta.to.shared.u64 t, %1; cvt.u32.u64 %0, t; }" : "=r"(a) : "l"(p));
    return a;
}
__device__ __forceinline__ unsigned long long to_global(const void* p) {
    unsigned long long g;
    asm("cvta.to.global.u64 %0, %1;" : "=l"(g) : "l"(p));
    return g;
}
#define CP16(dst_s32, src_g64) \
    asm volatile("cp.async.cg.shared.global [%0], [%1], 16;" :: "r"(dst_s32), "l"(src_g64) : "memory")
#define CP_COMMIT() asm volatile("cp.async.commit_group;" ::: "memory")
#define CP_WAIT2()  asm volatile("cp.async.wait_group 2;" ::: "memory")

__device__ __forceinline__ void mma_f16(float c[4], uint32_t a0, uint32_t a1, uint32_t a2, uint32_t a3,
                                        uint32_t b0, uint32_t b1) {
    asm volatile("mma.sync.aligned.m16n8k16.row.col.f32.f16.f16.f32 "
                 "{%0,%1,%2,%3}, {%4,%5,%6,%7}, {%8,%9}, {%0,%1,%2,%3};"
                 : "+f"(c[0]), "+f"(c[1]), "+f"(c[2]), "+f"(c[3])
                 : "r"(a0), "r"(a1), "r"(a2), "r"(a3), "r"(b0), "r"(b1));
}
#define LDSM_X4(r0, r1, r2, r3, addr) \
    asm volatile("ldmatrix.sync.aligned.m8n8.x4.shared.b16 {%0,%1,%2,%3}, [%4];" \
                 : "=r"(r0), "=r"(r1), "=r"(r2), "=r"(r3) : "r"(addr))

__device__ __forceinline__ uint32_t hfma2u(uint32_t a, uint32_t b, uint32_t c) {
    uint32_t d;
    asm("fma.rn.f16x2 %0, %1, %2, %3;" : "=r"(d) : "r"(a), "r"(b), "r"(c));
    return d;
}
__device__ __forceinline__ int load_idx(const void* p, size_t pos, int is64) {
    return is64 ? (int)((const long long*)p)[pos] : ((const int*)p)[pos];
}

// -------------------- single prep kernel: fp16 conversions + permutes + idx detect ------------
__global__ __launch_bounds__(256)
void prep_kernel(const float* __restrict__ all_m, const float* __restrict__ m_b,
                 const float* __restrict__ pw, const float* __restrict__ W1,
                 const unsigned* __restrict__ idxw, int n_words,
                 int n_mentions, int batch, int n_ants) {
    if (blockIdx.x == 0 && threadIdx.x == 0) {
        unsigned acc = 0;
        int m = n_words < 256 ? n_words : 256;
        for (int i = 1; i < m; i += 2) acc |= idxw[i];
        g_idx64 = (acc == 0u) ? 1 : 0;
    }
    const long long n4a = (long long)n_mentions * EMB / 4;
    const long long nw1 = (long long)KSEG * HID;
    const long long nmb = (long long)batch * EMB;
    const long long npw = (long long)batch * n_ants * PW;
    const long long TOT = n4a + nw1 + nmb + npw;
    const long long stride = (long long)gridDim.x * blockDim.x;
    for (long long i = (long long)blockIdx.x * blockDim.x + threadIdx.x; i < TOT; i += stride) {
        if (i < n4a) {
            float4 v = ((const float4*)all_m)[i];
            __half2* d = (__half2*)(g_allm_h + i * 4);
            d[0] = __floats2half2_rn(v.x, v.y);
            d[1] = __floats2half2_rn(v.z, v.w);
        } else if (i < n4a + nw1) {
            long long j = i - n4a;
            int k = (int)(j / HID), n = (int)(j % HID);
            float v = W1[(size_t)(1024 + k) * HID + n];
            g_W1Th[(size_t)n * KSEG + (k & ~31) + permk(k & 31)] = __float2half_rn(v);
        } else if (i < n4a + nw1 + nmb) {
            long long j = i - n4a - nw1;
            int b = (int)(j >> 10), k = (int)(j & 1023);
            g_amb_hp[(size_t)b * EMB + (k & ~31) + permk(k & 31)] = __float2half_rn(m_b[j]);
        } else {
            long long j = i - n4a - nw1 - nmb;
            g_pw_h[j] = __float2half_rn(pw[j]);
        }
    }
}

// -------------------- fused fp16 pair kernel --------------------
// Block: 4 batch rows -> M=256, N=128, 512 threads / 16 warps, grid = batch/4 = 128.
// Warp (mi = wid&3, nh = wid>>2): rows [64mi,64mi+64), cols [32nh,32nh+32); bq == mi.
// A fragments via ldmatrix.x4. B'' = WB + am (.) WS folded in registers.
// 4-stage cp.async pipeline, ONE __syncthreads per chunk:
//   iter c: wait_group 2 (chunk c landed) -> barrier (all warps done with chunk c-1)
//           -> stage chunk c+3 into buffer (c+3)&3 == (c-1)&3 (freed by that barrier)
//           -> consume chunk c.
#define OFF_IDX    0                     // 256 ints
#define OFF_WOUT   1024                  // 128 f
#define OFF_APROJ  1536                  // 512 f
#define OFF_MB     3584                  // 4 x 1024 f fp32 mentions_batch rows
#define OFF_STAGE  19968
#define ST_A       0                     // 256 rows x 80 B (32 halfs + pad)
#define ST_AM      20480                 // 4 x 64 B (permuted fp16)
#define ST_WB      20736                 // 128 x 64 B (permuted fp16)
#define ST_WS      28928                 // 128 x 64 B
#define STAGE_B    37120
#define SMEM_TOTAL (OFF_STAGE + 4 * STAGE_B)   // 168448

struct StageCtx {
    unsigned long long allm_g, w1t_g, pw_g, amb_g;
    int b0, n_ants;
};

__device__ __forceinline__ void stage_chunk(int c, uint32_t sbase,
                                            const int* idx_s, const StageCtx& cx, int tid) {
    const uint32_t stg = sbase + OFF_STAGE + (uint32_t)(c & 3) * STAGE_B;
    if (c < 32) {
        const int ec = c * 32;
#pragma unroll
        for (int it = 0; it < 2; it++) {       // A: gathered bm rows [256][32] fp16
            int id = tid + it * 512;
            int r = id >> 2, f4 = id & 3;
            unsigned long long src = cx.allm_g + ((size_t)idx_s[r] * EMB + ec) * 2ull + f4 * 16;
            CP16(stg + ST_A + (uint32_t)(r * 80 + f4 * 16), src);
        }
#pragma unroll
        for (int it = 0; it < 2; it++) {       // WB / WS (permuted fp16)
            int id = tid + it * 512;
            int seg = id >> 9, n = (id >> 2) & 127, f4 = id & 3;
            unsigned long long src = cx.w1t_g +
                ((size_t)n * KSEG + (seg ? 1024 + ec : ec)) * 2ull + f4 * 16;
            CP16(stg + (seg ? ST_WS : ST_WB) + (uint32_t)(n * 64 + f4 * 16), src);
        }
        if (tid < 16) {                        // AM: permuted am chunk [4][32] fp16
            int q = tid >> 2, f4 = tid & 3;
            unsigned long long src = cx.amb_g + ((size_t)(cx.b0 + q) * EMB + ec) * 2ull + f4 * 16;
            CP16(stg + ST_AM + (uint32_t)(q * 64 + f4 * 16), src);
        }
    } else {
        const int pc = (c - 32) * 32;
#pragma unroll
        for (int it = 0; it < 2; it++) {       // A: pw values [256][32] fp16
            int id = tid + it * 512;
            int r = id >> 2, f4 = id & 3;
            int bq = r >> 6, a = r & 63; if (a >= cx.n_ants) a = cx.n_ants - 1;
            unsigned long long src = cx.pw_g +
                (((size_t)(cx.b0 + bq) * cx.n_ants + a) * PW + pc) * 2ull + f4 * 16;
            CP16(stg + ST_A + (uint32_t)(r * 80 + f4 * 16), src);
        }
        {                                      // B: W1p (permuted) into WB region
            int n = tid >> 2, f4 = tid & 3;
            unsigned long long src = cx.w1t_g + ((size_t)n * KSEG + 2048 + pc) * 2ull + f4 * 16;
            CP16(stg + ST_WB + (uint32_t)(n * 64 + f4 * 16), src);
        }
    }
}

__global__ __launch_bounds__(512, 1)
void pair_mma_kernel(const float* __restrict__ m_b,
                     const void*  __restrict__ top_idx,
                     const float* __restrict__ rough,
                     const float* __restrict__ W1,
                     const float* __restrict__ b1,
                     const float* __restrict__ W_out,
                     const float* __restrict__ b_out,
                     float* __restrict__ out,
                     int n_ants) {
    extern __shared__ char smem[];
    const uint32_t sbase = smem_u32(smem);
    const int tid  = threadIdx.x;
    const int lane = tid & 31;
    const int wid  = tid >> 5;
    const int t    = lane & 3;       // k lane within quad
    const int q    = lane >> 2;      // row/col lane (0..7)
    const int b0   = blockIdx.x * 4;
    const int mi   = wid & 3;        // m-tile: rows [64mi,64mi+64); == bq
    const int nh   = wid >> 2;       // n-quarter: cols [32nh,32nh+32)
    const int rb   = mi * 64, nb = nh * 32;

    int*   idx_s   = (int*)(smem + OFF_IDX);
    float* wout_s  = (float*)(smem + OFF_WOUT);
    float* aproj_s = (float*)(smem + OFF_APROJ);
    float* mb_s    = (float*)(smem + OFF_MB);

    StageCtx cx;
    cx.allm_g = to_global(g_allm_h);
    cx.w1t_g  = to_global(g_W1Th);
    cx.pw_g   = to_global(g_pw_h);
    cx.amb_g  = to_global(g_amb_hp);
    cx.b0 = b0; cx.n_ants = n_ants;

    if (tid < 256) {
        int a = tid & 63; if (a >= n_ants) a = n_ants - 1;
        idx_s[tid] = load_idx(top_idx, (size_t)(b0 + (tid >> 6)) * n_ants + a, g_idx64);
    }
    if (tid < 128) wout_s[tid] = W_out[tid];
    {   // fp32 mentions_batch rows b0..b0+3 into smem (exact aproj inputs)
        const float4* src = (const float4*)(m_b + (size_t)b0 * EMB);
#pragma unroll
        for (int i2 = 0; i2 < 2; i2++) ((float4*)mb_s)[tid + i2 * 512] = src[tid + i2 * 512];
    }
    __syncthreads();

    stage_chunk(0, sbase, idx_s, cx, tid); CP_COMMIT();
    stage_chunk(1, sbase, idx_s, cx, tid); CP_COMMIT();
    stage_chunk(2, sbase, idx_s, cx, tid); CP_COMMIT();

    // accumulators: 4 m-frags x 4 n-frags x 4 (fp32)
    float acc[4][4][4];
#pragma unroll
    for (int i = 0; i < 4; i++)
#pragma unroll
        for (int nf = 0; nf < 4; nf++)
#pragma unroll
            for (int r = 0; r < 4; r++) acc[i][nf][r] = 0.f;

    // aproj: thread = (abq = tid>>7, ng = (tid>>2)&31, ks = tid&3); owns n = 4ng..4ng+3, k-shard ks
    const int abq = tid >> 7, ng = (tid >> 2) & 31, ks = tid & 3;
    float4 apacc = make_float4(0.f, 0.f, 0.f, 0.f);

    // ldmatrix lane base: row rb + (lane&15), k-half (lane>>4)
    const uint32_t a_lane_off = (uint32_t)((rb + (lane & 15)) * 80 + (lane >> 4) * 16);

    for (int c = 0; c < NCHUNK; c++) {
        CP_WAIT2();                            // chunk c landed (chunks c+1, c+2 in flight)
        __syncthreads();                       // all warps finished consuming chunk c-1

        if (c + 3 < NCHUNK) stage_chunk(c + 3, sbase, idx_s, cx, tid);
        CP_COMMIT();                           // keep group numbering stable

        const char* stp = smem + OFF_STAGE + (c & 3) * STAGE_B;
        const uint32_t stu = sbase + OFF_STAGE + (uint32_t)(c & 3) * STAGE_B;
        const bool has_sim = (c < 32);

        // B'' fold in registers: bpp[nf] = {b0s0, b1s0, b0s1, b1s1} half2s
        uint32_t bpp[4][4];
        {
            uint4 am4 = make_uint4(0, 0, 0, 0);
            if (has_sim) am4 = *(const uint4*)(stp + ST_AM + mi * 64 + t * 16);
#pragma unroll
            for (int nf = 0; nf < 4; nf++) {
                int n = nb + nf * 8 + q;
                uint4 wb = *(const uint4*)(stp + ST_WB + n * 64 + t * 16);
                if (has_sim) {
                    uint4 ws = *(const uint4*)(stp + ST_WS + n * 64 + t * 16);
                    bpp[nf][0] = hfma2u(am4.x, ws.x, wb.x);
                    bpp[nf][1] = hfma2u(am4.y, ws.y, wb.y);
                    bpp[nf][2] = hfma2u(am4.z, ws.z, wb.z);
                    bpp[nf][3] = hfma2u(am4.w, ws.w, wb.w);
                } else {
                    bpp[nf][0] = wb.x; bpp[nf][1] = wb.y;
                    bpp[nf][2] = wb.z; bpp[nf][3] = wb.w;
                }
            }
        }

#pragma unroll
        for (int s = 0; s < 2; s++) {          // two k16 steps
            uint32_t a_[4][4];
#pragma unroll
            for (int i = 0; i < 4; i++)
                LDSM_X4(a_[i][0], a_[i][1], a_[i][2], a_[i][3],
                        stu + a_lane_off + (uint32_t)(i * 16 * 80 + s * 32));
#pragma unroll
            for (int nf = 0; nf < 4; nf++) {
                uint32_t b0r = bpp[nf][2 * s], b1r = bpp[nf][2 * s + 1];
#pragma unroll
                for (int i = 0; i < 4; i++)
                    mma_f16(acc[i][nf], a_[i][0], a_[i][1], a_[i][2], a_[i][3], b0r, b1r);
            }
        }

        if (has_sim) {                          // aproj: 8 x (LDG.128 W1 + smem mb + 4 FMA)
            const int kbase = c * 32 + ks * 8;
            const float* mbr = mb_s + abq * EMB + kbase;
#pragma unroll
            for (int kk = 0; kk < 8; kk++) {
                float4 w4 = __ldg((const float4*)(W1 + (size_t)(kbase + kk) * HID) + ng);
                float m = mbr[kk];
                apacc.x += m * w4.x; apacc.y += m * w4.y;
                apacc.z += m * w4.z; apacc.w += m * w4.w;
            }
        }
    }
    __syncthreads();                            // all consumption done before buffer reuse

    // ---- epilogue: reduce aproj k-shards, then scores ----
    float* part2 = (float*)(smem + OFF_STAGE);           // [512 outs][4 shards]
    part2[(abq * 128 + ng * 4 + 0) * 4 + ks] = apacc.x;
    part2[(abq * 128 + ng * 4 + 1) * 4 + ks] = apacc.y;
    part2[(abq * 128 + ng * 4 + 2) * 4 + ks] = apacc.z;
    part2[(abq * 128 + ng * 4 + 3) * 4 + ks] = apacc.w;
    __syncthreads();
    {
        int n = tid & 127;
        aproj_s[tid] = b1[n] + part2[tid * 4] + part2[tid * 4 + 1]
                             + part2[tid * 4 + 2] + part2[tid * 4 + 3];
    }
    __syncthreads();

    float* part = (float*)(smem + OFF_STAGE + 8192);     // [256][4] score partials
    const float  bo  = __ldg(b_out);
    const float* apq = aproj_s + mi * 128;
#pragma unroll
    for (int i = 0; i < 4; i++) {
        float s0 = 0.f, s1 = 0.f;               // rows rb+16i+q, rb+16i+q+8
#pragma unroll
        for (int nf = 0; nf < 4; nf++) {
            int n0 = nb + nf * 8 + 2 * t, n1 = n0 + 1;
            float w0 = wout_s[n0], w1 = wout_s[n1];
            float ap0 = apq[n0], ap1 = apq[n1];
            float h;
            h = acc[i][nf][0] + ap0; h = fmaxf(h, 0.f) + 0.01f * fminf(h, 0.f); s0 += h * w0;
            h = acc[i][nf][1] + ap1; h = fmaxf(h, 0.f) + 0.01f * fminf(h, 0.f); s0 += h * w1;
            h = acc[i][nf][2] + ap0; h = fmaxf(h, 0.f) + 0.01f * fminf(h, 0.f); s1 += h * w0;
            h = acc[i][nf][3] + ap1; h = fmaxf(h, 0.f) + 0.01f * fminf(h, 0.f); s1 += h * w1;
        }
        s0 += __shfl_xor_sync(0xffffffffu, s0, 1);
        s0 += __shfl_xor_sync(0xffffffffu, s0, 2);
        s1 += __shfl_xor_sync(0xffffffffu, s1, 1);
        s1 += __shfl_xor_sync(0xffffffffu, s1, 2);
        if (t == 0) {
            part[(rb + 16 * i + q) * 4 + nh]     = s0;
            part[(rb + 16 * i + q + 8) * 4 + nh] = s1;
        }
    }
    __syncthreads();

    if (tid < 256) {
        float sc = part[tid * 4] + part[tid * 4 + 1] + part[tid * 4 + 2] + part[tid * 4 + 3];
        int a = tid & 63, bg = b0 + (tid >> 6);
        if (a < n_ants)
            out[(size_t)bg * (n_ants + 1) + 1 + a] =
                rough[(size_t)bg * n_ants + a] + bo + sc;
        if (a == 0) out[(size_t)bg * (n_ants + 1)] = EPSV;
    }
}

// -------------------- launch --------------------
extern "C" void kernel_launch(void* const* d_in, const int* in_sizes, int n_in,
                              void* d_out, int out_size) {
    const float* all_m = (const float*)d_in[0];
    const float* m_b   = (const float*)d_in[1];
    const float* pw    = (const float*)d_in[2];
    const void*  idx   = d_in[3];
    const float* rough = (const float*)d_in[4];
    const float* W1    = (const float*)d_in[5];
    const float* b1    = (const float*)d_in[6];
    const float* Wo    = (const float*)d_in[7];
    const float* bo    = (const float*)d_in[8];
    float* out = (float*)d_out;

    const int n_mentions = in_sizes[0] / EMB;  // 10000
    const int batch      = in_sizes[1] / EMB;  // 512
    const int n_ants     = in_sizes[3] / batch;// 50

    cudaFuncSetAttribute(pair_mma_kernel,
                         cudaFuncAttributeMaxDynamicSharedMemorySize, SMEM_TOTAL);

    prep_kernel<<<1184, 256>>>(all_m, m_b, pw, W1, (const unsigned*)idx, in_sizes[3],
                               n_mentions, batch, n_ants);
    pair_mma_kernel<<<batch / 4, 512, SMEM_TOTAL>>>(m_b, idx, rough,
                                                    W1, b1, Wo, bo, out, n_ants);
}

// round 13
// speedup vs baseline: 1.1853x; 1.1343x over previous
#include <cuda_runtime.h>
#include <cuda_fp16.h>
#include <cstdint>

#define EMB    1024
#define HID    128
#define PW     64
#define KSEG   2112          // W1 rows [1024,3136): bm(1024) + sim(1024) + pw(64)
#define NCHUNK 34            // 32 e-chunks (K=32, sim folded into B) + 2 pw chunks
#define NSTG   5
#define EPSV   1e-7f
#define PREP_MAIN_BLKS 1184
#define APROJ_BLKS     128

// -------------------- device scratch (no allocs allowed) --------------------
__device__ __half g_allm_h[10016 * EMB];   // fp16 all_mentions, plain layout
__device__ __half g_W1Th[HID * KSEG];      // fp16 W1^T, per-32-chunk fragment-permuted
__device__ __half g_amb_hp[512 * EMB];     // fp16 mentions_batch, fragment-permuted
__device__ __half g_pw_h[512 * 64 * PW];   // fp16 pw, plain
__device__ float  g_Aproj[512 * HID];      // fp32 m_b @ W1[0:1024] + b1
__device__ int    g_idx64;

// fragment permutation within a 32-k chunk (matches m16n8k16 B/mult layout):
// t=(k>>1)&3, hi=(k>>3)&1, b=k&1, h16=k>>4  ->  pos = t*8 + h16*4 + hi*2 + b
__device__ __forceinline__ int permk(int kk) {
    return ((kk >> 1) & 3) * 8 + (kk >> 4) * 4 + ((kk >> 3) & 1) * 2 + (kk & 1);
}

// -------------------- helpers --------------------
__device__ __forceinline__ uint32_t smem_u32(const void* p) {
    uint32_t a;
    asm("{ .reg .u64 t; cvta.to.shared.u64 t, %1; cvt.u32.u64 %0, t; }" : "=r"(a) : "l"(p));
    return a;
}
__device__ __forceinline__ unsigned long long to_global(const void* p) {
    unsigned long long g;
    asm("cvta.to.global.u64 %0, %1;" : "=l"(g) : "l"(p));
    return g;
}
#define CP16(dst_s32, src_g64) \
    asm volatile("cp.async.cg.shared.global [%0], [%1], 16;" :: "r"(dst_s32), "l"(src_g64) : "memory")
#define CP_COMMIT() asm volatile("cp.async.commit_group;" ::: "memory")
#define CP_WAIT3()  asm volatile("cp.async.wait_group 3;" ::: "memory")

__device__ __forceinline__ void mma_f16(float c[4], uint32_t a0, uint32_t a1, uint32_t a2, uint32_t a3,
                                        uint32_t b0, uint32_t b1) {
    asm volatile("mma.sync.aligned.m16n8k16.row.col.f32.f16.f16.f32 "
                 "{%0,%1,%2,%3}, {%4,%5,%6,%7}, {%8,%9}, {%0,%1,%2,%3};"
                 : "+f"(c[0]), "+f"(c[1]), "+f"(c[2]), "+f"(c[3])
                 : "r"(a0), "r"(a1), "r"(a2), "r"(a3), "r"(b0), "r"(b1));
}
#define LDSM_X4(r0, r1, r2, r3, addr) \
    asm volatile("ldmatrix.sync.aligned.m8n8.x4.shared.b16 {%0,%1,%2,%3}, [%4];" \
                 : "=r"(r0), "=r"(r1), "=r"(r2), "=r"(r3) : "r"(addr))

__device__ __forceinline__ uint32_t hfma2u(uint32_t a, uint32_t b, uint32_t c) {
    uint32_t d;
    asm("fma.rn.f16x2 %0, %1, %2, %3;" : "=r"(d) : "r"(a), "r"(b), "r"(c));
    return d;
}
__device__ __forceinline__ int load_idx(const void* p, size_t pos, int is64) {
    return is64 ? (int)((const long long*)p)[pos] : ((const int*)p)[pos];
}

// -------------------- prep kernel: conversions/permutes + idx detect + Aproj ------------------
// Blocks [0, PREP_MAIN_BLKS): grid-stride fp16 conversion of all_m / W1T / amb / pw.
// Blocks [PREP_MAIN_BLKS, +APROJ_BLKS): block bi computes g_Aproj rows [4bi, 4bi+4) exactly (fp32).
__global__ __launch_bounds__(256)
void prep_kernel(const float* __restrict__ all_m, const float* __restrict__ m_b,
                 const float* __restrict__ pw, const float* __restrict__ W1,
                 const float* __restrict__ b1,
                 const unsigned* __restrict__ idxw, int n_words,
                 int n_mentions, int batch, int n_ants) {
    const int tid = threadIdx.x;
    if (blockIdx.x >= PREP_MAIN_BLKS) {
        // ---- Aproj path ----
        __shared__ float mbs[4 * EMB];       // 16 KB
        __shared__ float red[256 * 4];
        const int bi = blockIdx.x - PREP_MAIN_BLKS;
        const int r0 = bi * 4;
        for (int i = tid; i < EMB; i += 256)
            ((float4*)mbs)[i] = ((const float4*)(m_b + (size_t)r0 * EMB))[i];
        __syncthreads();
        const int n = tid & 127, kh = tid >> 7;
        float a0 = 0.f, a1 = 0.f, a2 = 0.f, a3 = 0.f;
        const float* wp = W1 + n;
#pragma unroll 4
        for (int k = kh * 512; k < kh * 512 + 512; k++) {
            float w = __ldg(wp + (size_t)k * HID);
            a0 += mbs[k] * w;
            a1 += mbs[EMB + k] * w;
            a2 += mbs[2 * EMB + k] * w;
            a3 += mbs[3 * EMB + k] * w;
        }
        red[tid * 4 + 0] = a0; red[tid * 4 + 1] = a1;
        red[tid * 4 + 2] = a2; red[tid * 4 + 3] = a3;
        __syncthreads();
        if (kh == 0) {
            float bb = b1[n];
            int o = (tid + 128) * 4;
#pragma unroll
            for (int j = 0; j < 4; j++)
                g_Aproj[(size_t)(r0 + j) * HID + n] = red[tid * 4 + j] + red[o + j] + bb;
        }
        return;
    }
    if (blockIdx.x == 0 && tid == 0) {
        unsigned acc = 0;
        int m = n_words < 256 ? n_words : 256;
        for (int i = 1; i < m; i += 2) acc |= idxw[i];
        g_idx64 = (acc == 0u) ? 1 : 0;
    }
    const long long n4a = (long long)n_mentions * EMB / 4;
    const long long nw1 = (long long)KSEG * HID;
    const long long nmb = (long long)batch * EMB;
    const long long npw = (long long)batch * n_ants * PW;
    const long long TOT = n4a + nw1 + nmb + npw;
    const long long stride = (long long)PREP_MAIN_BLKS * 256;
    for (long long i = (long long)blockIdx.x * 256 + tid; i < TOT; i += stride) {
        if (i < n4a) {
            float4 v = ((const float4*)all_m)[i];
            __half2* d = (__half2*)(g_allm_h + i * 4);
            d[0] = __floats2half2_rn(v.x, v.y);
            d[1] = __floats2half2_rn(v.z, v.w);
        } else if (i < n4a + nw1) {
            long long j = i - n4a;
            int k = (int)(j / HID), n = (int)(j % HID);
            float v = W1[(size_t)(1024 + k) * HID + n];
            g_W1Th[(size_t)n * KSEG + (k & ~31) + permk(k & 31)] = __float2half_rn(v);
        } else if (i < n4a + nw1 + nmb) {
            long long j = i - n4a - nw1;
            int b = (int)(j >> 10), k = (int)(j & 1023);
            g_amb_hp[(size_t)b * EMB + (k & ~31) + permk(k & 31)] = __float2half_rn(m_b[j]);
        } else {
            long long j = i - n4a - nw1 - nmb;
            g_pw_h[j] = __float2half_rn(pw[j]);
        }
    }
}

// -------------------- fused fp16 pair kernel --------------------
// Block: 4 batch rows -> M=256, N=128, 512 threads / 16 warps, grid = batch/4 = 128.
// Warp (mi = wid&3, nh = wid>>2): rows [64mi,64mi+64), cols [32nh,32nh+32); bq == mi.
// A fragments via ldmatrix.x4. B'' = WB + am (.) WS folded in registers.
// 5-stage cp.async pipeline, one __syncthreads per chunk:
//   iter c: wait_group 3 (chunk c landed) -> barrier (chunk c-1 fully consumed)
//           -> stage chunk c+4 into buffer (c+4)%5 == (c-1)%5 -> consume chunk c.
#define OFF_IDX    0                     // 256 ints
#define OFF_WOUT   1024                  // 128 f
#define OFF_APROJ  1536                  // 512 f
#define OFF_STAGE  4096
#define ST_A       0                     // 256 rows x 80 B (32 halfs + pad)
#define ST_AM      20480                 // 4 x 64 B (permuted fp16)
#define ST_WB      20736                 // 128 x 64 B (permuted fp16)
#define ST_WS      28928                 // 128 x 64 B
#define STAGE_B    37120
#define SMEM_TOTAL (OFF_STAGE + NSTG * STAGE_B)   // 189696

struct StageCtx {
    unsigned long long allm_g, w1t_g, pw_g, amb_g;
    int b0, n_ants;
};

__device__ __forceinline__ void stage_chunk(int c, int buf, uint32_t sbase,
                                            const int* idx_s, const StageCtx& cx, int tid) {
    const uint32_t stg = sbase + OFF_STAGE + (uint32_t)buf * STAGE_B;
    if (c < 32) {
        const int ec = c * 32;
#pragma unroll
        for (int it = 0; it < 2; it++) {       // A: gathered bm rows [256][32] fp16
            int id = tid + it * 512;
            int r = id >> 2, f4 = id & 3;
            unsigned long long src = cx.allm_g + ((size_t)idx_s[r] * EMB + ec) * 2ull + f4 * 16;
            CP16(stg + ST_A + (uint32_t)(r * 80 + f4 * 16), src);
        }
#pragma unroll
        for (int it = 0; it < 2; it++) {       // WB / WS (permuted fp16)
            int id = tid + it * 512;
            int seg = id >> 9, n = (id >> 2) & 127, f4 = id & 3;
            unsigned long long src = cx.w1t_g +
                ((size_t)n * KSEG + (seg ? 1024 + ec : ec)) * 2ull + f4 * 16;
            CP16(stg + (seg ? ST_WS : ST_WB) + (uint32_t)(n * 64 + f4 * 16), src);
        }
        if (tid < 16) {                        // AM: permuted am chunk [4][32] fp16
            int q = tid >> 2, f4 = tid & 3;
            unsigned long long src = cx.amb_g + ((size_t)(cx.b0 + q) * EMB + ec) * 2ull + f4 * 16;
            CP16(stg + ST_AM + (uint32_t)(q * 64 + f4 * 16), src);
        }
    } else {
        const int pc = (c - 32) * 32;
#pragma unroll
        for (int it = 0; it < 2; it++) {       // A: pw values [256][32] fp16
            int id = tid + it * 512;
            int r = id >> 2, f4 = id & 3;
            int bq = r >> 6, a = r & 63; if (a >= cx.n_ants) a = cx.n_ants - 1;
            unsigned long long src = cx.pw_g +
                (((size_t)(cx.b0 + bq) * cx.n_ants + a) * PW + pc) * 2ull + f4 * 16;
            CP16(stg + ST_A + (uint32_t)(r * 80 + f4 * 16), src);
        }
        {                                      // B: W1p (permuted) into WB region
            int n = tid >> 2, f4 = tid & 3;
            unsigned long long src = cx.w1t_g + ((size_t)n * KSEG + 2048 + pc) * 2ull + f4 * 16;
            CP16(stg + ST_WB + (uint32_t)(n * 64 + f4 * 16), src);
        }
    }
}

__global__ __launch_bounds__(512, 1)
void pair_mma_kernel(const void*  __restrict__ top_idx,
                     const float* __restrict__ rough,
                     const float* __restrict__ W_out,
                     const float* __restrict__ b_out,
                     float* __restrict__ out,
                     int n_ants) {
    extern __shared__ char smem[];
    const uint32_t sbase = smem_u32(smem);
    const int tid  = threadIdx.x;
    const int lane = tid & 31;
    const int wid  = tid >> 5;
    const int t    = lane & 3;       // k lane within quad
    const int q    = lane >> 2;      // row/col lane (0..7)
    const int b0   = blockIdx.x * 4;
    const int mi   = wid & 3;        // m-tile: rows [64mi,64mi+64); == bq
    const int nh   = wid >> 2;       // n-quarter: cols [32nh,32nh+32)
    const int rb   = mi * 64, nb = nh * 32;

    int*   idx_s   = (int*)(smem + OFF_IDX);
    float* wout_s  = (float*)(smem + OFF_WOUT);
    float* aproj_s = (float*)(smem + OFF_APROJ);

    StageCtx cx;
    cx.allm_g = to_global(g_allm_h);
    cx.w1t_g  = to_global(g_W1Th);
    cx.pw_g   = to_global(g_pw_h);
    cx.amb_g  = to_global(g_amb_hp);
    cx.b0 = b0; cx.n_ants = n_ants;

    if (tid < 256) {
        int a = tid & 63; if (a >= n_ants) a = n_ants - 1;
        idx_s[tid] = load_idx(top_idx, (size_t)(b0 + (tid >> 6)) * n_ants + a, g_idx64);
    }
    if (tid < 128) wout_s[tid] = W_out[tid];
    __syncthreads();

    stage_chunk(0, 0, sbase, idx_s, cx, tid); CP_COMMIT();
    stage_chunk(1, 1, sbase, idx_s, cx, tid); CP_COMMIT();
    stage_chunk(2, 2, sbase, idx_s, cx, tid); CP_COMMIT();
    stage_chunk(3, 3, sbase, idx_s, cx, tid); CP_COMMIT();

    // accumulators: 4 m-frags x 4 n-frags x 4 (fp32)
    float acc[4][4][4];
#pragma unroll
    for (int i = 0; i < 4; i++)
#pragma unroll
        for (int nf = 0; nf < 4; nf++)
#pragma unroll
            for (int r = 0; r < 4; r++) acc[i][nf][r] = 0.f;

    // ldmatrix lane base: row rb + (lane&15), k-half (lane>>4)
    const uint32_t a_lane_off = (uint32_t)((rb + (lane & 15)) * 80 + (lane >> 4) * 16);

    int bc = 0;                                // consume buffer = c % 5
    for (int c = 0; c < NCHUNK; c++) {
        CP_WAIT3();                            // chunk c landed (c+1..c+3 may be in flight)
        __syncthreads();                       // all warps finished consuming chunk c-1

        if (c + 4 < NCHUNK)
            stage_chunk(c + 4, (bc == 0) ? 4 : bc - 1, sbase, idx_s, cx, tid);
        CP_COMMIT();                           // keep group numbering stable

        const char* stp = smem + OFF_STAGE + bc * STAGE_B;
        const uint32_t stu = sbase + OFF_STAGE + (uint32_t)bc * STAGE_B;
        const bool has_sim = (c < 32);

        // B'' fold in registers: bpp[nf] = {b0s0, b1s0, b0s1, b1s1} half2s
        uint32_t bpp[4][4];
        {
            uint4 am4 = make_uint4(0, 0, 0, 0);
            if (has_sim) am4 = *(const uint4*)(stp + ST_AM + mi * 64 + t * 16);
#pragma unroll
            for (int nf = 0; nf < 4; nf++) {
                int n = nb + nf * 8 + q;
                uint4 wb = *(const uint4*)(stp + ST_WB + n * 64 + t * 16);
                if (has_sim) {
                    uint4 ws = *(const uint4*)(stp + ST_WS + n * 64 + t * 16);
                    bpp[nf][0] = hfma2u(am4.x, ws.x, wb.x);
                    bpp[nf][1] = hfma2u(am4.y, ws.y, wb.y);
                    bpp[nf][2] = hfma2u(am4.z, ws.z, wb.z);
                    bpp[nf][3] = hfma2u(am4.w, ws.w, wb.w);
                } else {
                    bpp[nf][0] = wb.x; bpp[nf][1] = wb.y;
                    bpp[nf][2] = wb.z; bpp[nf][3] = wb.w;
                }
            }
        }

#pragma unroll
        for (int s = 0; s < 2; s++) {          // two k16 steps
            uint32_t a_[4][4];
#pragma unroll
            for (int i = 0; i < 4; i++)
                LDSM_X4(a_[i][0], a_[i][1], a_[i][2], a_[i][3],
                        stu + a_lane_off + (uint32_t)(i * 16 * 80 + s * 32));
#pragma unroll
            for (int nf = 0; nf < 4; nf++) {
                uint32_t b0r = bpp[nf][2 * s], b1r = bpp[nf][2 * s + 1];
#pragma unroll
                for (int i = 0; i < 4; i++)
                    mma_f16(acc[i][nf], a_[i][0], a_[i][1], a_[i][2], a_[i][3], b0r, b1r);
            }
        }
        bc = (bc == 4) ? 0 : bc + 1;
    }

    // ---- epilogue ----
    aproj_s[tid] = g_Aproj[(size_t)(b0 + (tid >> 7)) * HID + (tid & 127)];
    __syncthreads();                            // aproj visible + stage buffers reusable

    float* part = (float*)(smem + OFF_STAGE);   // [256][4] score partials
    const float  bo  = __ldg(b_out);
    const float* apq = aproj_s + mi * 128;
#pragma unroll
    for (int i = 0; i < 4; i++) {
        float s0 = 0.f, s1 = 0.f;               // rows rb+16i+q, rb+16i+q+8
#pragma unroll
        for (int nf = 0; nf < 4; nf++) {
            int n0 = nb + nf * 8 + 2 * t, n1 = n0 + 1;
            float w0 = wout_s[n0], w1 = wout_s[n1];
            float ap0 = apq[n0], ap1 = apq[n1];
            float h;
            h = acc[i][nf][0] + ap0; h = fmaxf(h, 0.f) + 0.01f * fminf(h, 0.f); s0 += h * w0;
            h = acc[i][nf][1] + ap1; h = fmaxf(h, 0.f) + 0.01f * fminf(h, 0.f); s0 += h * w1;
            h = acc[i][nf][2] + ap0; h = fmaxf(h, 0.f) + 0.01f * fminf(h, 0.f); s1 += h * w0;
            h = acc[i][nf][3] + ap1; h = fmaxf(h, 0.f) + 0.01f * fminf(h, 0.f); s1 += h * w1;
        }
        s0 += __shfl_xor_sync(0xffffffffu, s0, 1);
        s0 += __shfl_xor_sync(0xffffffffu, s0, 2);
        s1 += __shfl_xor_sync(0xffffffffu, s1, 1);
        s1 += __shfl_xor_sync(0xffffffffu, s1, 2);
        if (t == 0) {
            part[(rb + 16 * i + q) * 4 + nh]     = s0;
            part[(rb + 16 * i + q + 8) * 4 + nh] = s1;
        }
    }
    __syncthreads();

    if (tid < 256) {
        float sc = part[tid * 4] + part[tid * 4 + 1] + part[tid * 4 + 2] + part[tid * 4 + 3];
        int a = tid & 63, bg = b0 + (tid >> 6);
        if (a < n_ants)
            out[(size_t)bg * (n_ants + 1) + 1 + a] =
                rough[(size_t)bg * n_ants + a] + bo + sc;
        if (a == 0) out[(size_t)bg * (n_ants + 1)] = EPSV;
    }
}

// -------------------- launch --------------------
extern "C" void kernel_launch(void* const* d_in, const int* in_sizes, int n_in,
                              void* d_out, int out_size) {
    const float* all_m = (const float*)d_in[0];
    const float* m_b   = (const float*)d_in[1];
    const float* pw    = (const float*)d_in[2];
    const void*  idx   = d_in[3];
    const float* rough = (const float*)d_in[4];
    const float* W1    = (const float*)d_in[5];
    const float* b1    = (const float*)d_in[6];
    const float* Wo    = (const float*)d_in[7];
    const float* bo    = (const float*)d_in[8];
    float* out = (float*)d_out;

    const int n_mentions = in_sizes[0] / EMB;  // 10000
    const int batch      = in_sizes[1] / EMB;  // 512
    const int n_ants     = in_sizes[3] / batch;// 50

    cudaFuncSetAttribute(pair_mma_kernel,
                         cudaFuncAttributeMaxDynamicSharedMemorySize, SMEM_TOTAL);

    prep_kernel<<<PREP_MAIN_BLKS + APROJ_BLKS, 256>>>(all_m, m_b, pw, W1, b1,
                                                      (const unsigned*)idx, in_sizes[3],
                                                      n_mentions, batch, n_ants);
    pair_mma_kernel<<<batch / 4, 512, SMEM_TOTAL>>>(idx, rough, Wo, bo, out, n_ants);
}

// round 14
// speedup vs baseline: 1.1870x; 1.0014x over previous
#include <cuda_runtime.h>
#include <cuda_fp16.h>
#include <cstdint>

#define EMB    1024
#define HID    128
#define PW     64
#define KSEG   2112          // W1 rows [1024,3136): bm(1024) + sim(1024) + pw(64)
#define NCHUNK 17            // 16 e-chunks (K=64, sim folded into B) + 1 pw chunk (K=64)
#define EPSV   1e-7f
#define PREP_MAIN_BLKS 1184
#define APROJ_BLKS     128

// -------------------- device scratch (no allocs allowed) --------------------
__device__ __half g_allm_h[10016 * EMB];   // fp16 all_mentions, plain layout
__device__ __half g_W1Th[HID * KSEG];      // fp16 W1^T, per-32-chunk fragment-permuted
__device__ __half g_amb_hp[512 * EMB];     // fp16 mentions_batch, fragment-permuted
__device__ __half g_pw_h[512 * 64 * PW];   // fp16 pw, plain
__device__ float  g_Aproj[512 * HID];      // fp32 m_b @ W1[0:1024] + b1
__device__ int    g_idx64;

// fragment permutation within a 32-k chunk (matches m16n8k16 B/mult layout):
// t=(k>>1)&3, hi=(k>>3)&1, b=k&1, h16=k>>4  ->  pos = t*8 + h16*4 + hi*2 + b
__device__ __forceinline__ int permk(int kk) {
    return ((kk >> 1) & 3) * 8 + (kk >> 4) * 4 + ((kk >> 3) & 1) * 2 + (kk & 1);
}

// -------------------- helpers --------------------
__device__ __forceinline__ uint32_t smem_u32(const void* p) {
    uint32_t a;
    asm("{ .reg .u64 t; cvta.to.shared.u64 t, %1; cvt.u32.u64 %0, t; }" : "=r"(a) : "l"(p));
    return a;
}
__device__ __forceinline__ unsigned long long to_global(const void* p) {
    unsigned long long g;
    asm("cvta.to.global.u64 %0, %1;" : "=l"(g) : "l"(p));
    return g;
}
#define CP16(dst_s32, src_g64) \
    asm volatile("cp.async.cg.shared.global [%0], [%1], 16;" :: "r"(dst_s32), "l"(src_g64) : "memory")
#define CP_COMMIT() asm volatile("cp.async.commit_group;" ::: "memory")
#define CP_WAIT1()  asm volatile("cp.async.wait_group 1;" ::: "memory")

__device__ __forceinline__ void mma_f16(float c[4], uint32_t a0, uint32_t a1, uint32_t a2, uint32_t a3,
                                        uint32_t b0, uint32_t b1) {
    asm volatile("mma.sync.aligned.m16n8k16.row.col.f32.f16.f16.f32 "
                 "{%0,%1,%2,%3}, {%4,%5,%6,%7}, {%8,%9}, {%0,%1,%2,%3};"
                 : "+f"(c[0]), "+f"(c[1]), "+f"(c[2]), "+f"(c[3])
                 : "r"(a0), "r"(a1), "r"(a2), "r"(a3), "r"(b0), "r"(b1));
}
#define LDSM_X4(r0, r1, r2, r3, addr) \
    asm volatile("ldmatrix.sync.aligned.m8n8.x4.shared.b16 {%0,%1,%2,%3}, [%4];" \
                 : "=r"(r0), "=r"(r1), "=r"(r2), "=r"(r3) : "r"(addr))

__device__ __forceinline__ uint32_t hfma2u(uint32_t a, uint32_t b, uint32_t c) {
    uint32_t d;
    asm("fma.rn.f16x2 %0, %1, %2, %3;" : "=r"(d) : "r"(a), "r"(b), "r"(c));
    return d;
}
__device__ __forceinline__ int load_idx(const void* p, size_t pos, int is64) {
    return is64 ? (int)((const long long*)p)[pos] : ((const int*)p)[pos];
}

// -------------------- prep kernel: conversions/permutes + idx detect + Aproj ------------------
__global__ __launch_bounds__(256)
void prep_kernel(const float* __restrict__ all_m, const float* __restrict__ m_b,
                 const float* __restrict__ pw, const float* __restrict__ W1,
                 const float* __restrict__ b1,
                 const unsigned* __restrict__ idxw, int n_words,
                 int n_mentions, int batch, int n_ants) {
    const int tid = threadIdx.x;
    if (blockIdx.x >= PREP_MAIN_BLKS) {
        // ---- Aproj path: block bi -> g_Aproj rows [4bi, 4bi+4), exact fp32 ----
        __shared__ float mbs[4 * EMB];
        __shared__ float red[256 * 4];
        const int bi = blockIdx.x - PREP_MAIN_BLKS;
        const int r0 = bi * 4;
        for (int i = tid; i < EMB; i += 256)
            ((float4*)mbs)[i] = ((const float4*)(m_b + (size_t)r0 * EMB))[i];
        __syncthreads();
        const int n = tid & 127, kh = tid >> 7;
        float a0 = 0.f, a1 = 0.f, a2 = 0.f, a3 = 0.f;
        const float* wp = W1 + n;
#pragma unroll 4
        for (int k = kh * 512; k < kh * 512 + 512; k++) {
            float w = __ldg(wp + (size_t)k * HID);
            a0 += mbs[k] * w;
            a1 += mbs[EMB + k] * w;
            a2 += mbs[2 * EMB + k] * w;
            a3 += mbs[3 * EMB + k] * w;
        }
        red[tid * 4 + 0] = a0; red[tid * 4 + 1] = a1;
        red[tid * 4 + 2] = a2; red[tid * 4 + 3] = a3;
        __syncthreads();
        if (kh == 0) {
            float bb = b1[n];
            int o = (tid + 128) * 4;
#pragma unroll
            for (int j = 0; j < 4; j++)
                g_Aproj[(size_t)(r0 + j) * HID + n] = red[tid * 4 + j] + red[o + j] + bb;
        }
        return;
    }
    if (blockIdx.x == 0 && tid == 0) {
        unsigned acc = 0;
        int m = n_words < 256 ? n_words : 256;
        for (int i = 1; i < m; i += 2) acc |= idxw[i];
        g_idx64 = (acc == 0u) ? 1 : 0;
    }
    const long long n4a = (long long)n_mentions * EMB / 4;
    const long long nw1 = (long long)KSEG * HID;
    const long long nmb = (long long)batch * EMB;
    const long long npw = (long long)batch * n_ants * PW;
    const long long TOT = n4a + nw1 + nmb + npw;
    const long long stride = (long long)PREP_MAIN_BLKS * 256;
    for (long long i = (long long)blockIdx.x * 256 + tid; i < TOT; i += stride) {
        if (i < n4a) {
            float4 v = ((const float4*)all_m)[i];
            __half2* d = (__half2*)(g_allm_h + i * 4);
            d[0] = __floats2half2_rn(v.x, v.y);
            d[1] = __floats2half2_rn(v.z, v.w);
        } else if (i < n4a + nw1) {
            long long j = i - n4a;
            int k = (int)(j / HID), n = (int)(j % HID);
            float v = W1[(size_t)(1024 + k) * HID + n];
            g_W1Th[(size_t)n * KSEG + (k & ~31) + permk(k & 31)] = __float2half_rn(v);
        } else if (i < n4a + nw1 + nmb) {
            long long j = i - n4a - nw1;
            int b = (int)(j >> 10), k = (int)(j & 1023);
            g_amb_hp[(size_t)b * EMB + (k & ~31) + permk(k & 31)] = __float2half_rn(m_b[j]);
        } else {
            long long j = i - n4a - nw1 - nmb;
            g_pw_h[j] = __float2half_rn(pw[j]);
        }
    }
}

// -------------------- fused fp16 pair kernel --------------------
// Block: 4 batch rows -> M=256, N=128, 512 threads / 16 warps, grid = batch/4 = 128.
// Warp (mi = wid&3, nh = wid>>2): rows [64mi,64mi+64), cols [32nh,32nh+32); bq == mi.
// K=64 chunks (two 32-k halves back-to-back) -> ONE barrier + ONE wait per 64 k.
// 3-stage cp.async pipeline: iter c: wait_group 1 (chunk c landed, c+1 in flight)
//   -> barrier (chunk c-1 consumed) -> stage c+2 into buffer (c+2)%3 == (c-1)%3 -> consume c.
#define OFF_IDX    0                     // 256 ints
#define OFF_WOUT   1024                  // 128 f
#define OFF_APROJ  1536                  // 512 f
#define OFF_STAGE  4096
#define ST_A       0                     // 256 rows x 144 B (64 halfs + 16B pad)
#define ST_AM      36864                 // 4 rows x 128 B (two permuted 32-k halves)
#define ST_WB      37376                 // 128 n x 128 B
#define ST_WS      53760                 // 128 n x 128 B
#define STAGE_B    70144
#define SMEM_TOTAL (OFF_STAGE + 3 * STAGE_B)   // 214528

struct StageCtx {
    unsigned long long allm_g, w1t_g, pw_g, amb_g;
    int b0, n_ants;
};

__device__ __forceinline__ void stage_chunk(int c, int buf, uint32_t sbase,
                                            const int* idx_s, const StageCtx& cx, int tid) {
    const uint32_t stg = sbase + OFF_STAGE + (uint32_t)buf * STAGE_B;
    if (c < 16) {
        const int ec = c * 64;
#pragma unroll
        for (int it = 0; it < 4; it++) {       // A: gathered bm rows [256][64] fp16
            int id = tid + it * 512;
            int r = id >> 3, f8 = id & 7;
            unsigned long long src = cx.allm_g + ((size_t)idx_s[r] * EMB + ec) * 2ull + f8 * 16;
            CP16(stg + ST_A + (uint32_t)(r * 144 + f8 * 16), src);
        }
#pragma unroll
        for (int it = 0; it < 4; it++) {       // WB / WS (permuted fp16, two 32-k halves)
            int id = tid + it * 512;
            int seg = id >> 10, n = (id >> 3) & 127, f8 = id & 7;
            unsigned long long src = cx.w1t_g +
                ((size_t)n * KSEG + (seg ? 1024 + ec : ec)) * 2ull + f8 * 16;
            CP16(stg + (seg ? ST_WS : ST_WB) + (uint32_t)(n * 128 + f8 * 16), src);
        }
        if (tid < 32) {                        // AM: permuted am chunk [4][64] fp16
            int q = tid >> 3, f8 = tid & 7;
            unsigned long long src = cx.amb_g + ((size_t)(cx.b0 + q) * EMB + ec) * 2ull + f8 * 16;
            CP16(stg + ST_AM + (uint32_t)(q * 128 + f8 * 16), src);
        }
    } else {
        // pw chunk: K = 64 = full PW
#pragma unroll
        for (int it = 0; it < 4; it++) {       // A: pw values [256][64] fp16
            int id = tid + it * 512;
            int r = id >> 3, f8 = id & 7;
            int bq = r >> 6, a = r & 63; if (a >= cx.n_ants) a = cx.n_ants - 1;
            unsigned long long src = cx.pw_g +
                ((size_t)(cx.b0 + bq) * cx.n_ants + a) * PW * 2ull + f8 * 16;
            CP16(stg + ST_A + (uint32_t)(r * 144 + f8 * 16), src);
        }
#pragma unroll
        for (int it = 0; it < 2; it++) {       // B: W1p (permuted) into WB region
            int id = tid + it * 512;
            int n = id >> 3, f8 = id & 7;
            unsigned long long src = cx.w1t_g + ((size_t)n * KSEG + 2048) * 2ull + f8 * 16;
            CP16(stg + ST_WB + (uint32_t)(n * 128 + f8 * 16), src);
        }
    }
}

__global__ __launch_bounds__(512, 1)
void pair_mma_kernel(const void*  __restrict__ top_idx,
                     const float* __restrict__ rough,
                     const float* __restrict__ W_out,
                     const float* __restrict__ b_out,
                     float* __restrict__ out,
                     int n_ants) {
    extern __shared__ char smem[];
    const uint32_t sbase = smem_u32(smem);
    const int tid  = threadIdx.x;
    const int lane = tid & 31;
    const int wid  = tid >> 5;
    const int t    = lane & 3;       // k lane within quad
    const int q    = lane >> 2;      // row/col lane (0..7)
    const int b0   = blockIdx.x * 4;
    const int mi   = wid & 3;        // m-tile: rows [64mi,64mi+64); == bq
    const int nh   = wid >> 2;       // n-quarter: cols [32nh,32nh+32)
    const int rb   = mi * 64, nb = nh * 32;

    int*   idx_s   = (int*)(smem + OFF_IDX);
    float* wout_s  = (float*)(smem + OFF_WOUT);
    float* aproj_s = (float*)(smem + OFF_APROJ);

    StageCtx cx;
    cx.allm_g = to_global(g_allm_h);
    cx.w1t_g  = to_global(g_W1Th);
    cx.pw_g   = to_global(g_pw_h);
    cx.amb_g  = to_global(g_amb_hp);
    cx.b0 = b0; cx.n_ants = n_ants;

    if (tid < 256) {
        int a = tid & 63; if (a >= n_ants) a = n_ants - 1;
        idx_s[tid] = load_idx(top_idx, (size_t)(b0 + (tid >> 6)) * n_ants + a, g_idx64);
    }
    if (tid < 128) wout_s[tid] = W_out[tid];
    __syncthreads();

    stage_chunk(0, 0, sbase, idx_s, cx, tid); CP_COMMIT();
    stage_chunk(1, 1, sbase, idx_s, cx, tid); CP_COMMIT();

    // accumulators: 4 m-frags x 4 n-frags x 4 (fp32)
    float acc[4][4][4];
#pragma unroll
    for (int i = 0; i < 4; i++)
#pragma unroll
        for (int nf = 0; nf < 4; nf++)
#pragma unroll
            for (int r = 0; r < 4; r++) acc[i][nf][r] = 0.f;

    // ldmatrix lane base: row rb + (lane&15), k-half (lane>>4); 144B pitch is conflict-free
    const uint32_t a_lane_off = (uint32_t)((rb + (lane & 15)) * 144 + (lane >> 4) * 16);

    int bc = 0;                                // consume buffer = c % 3
    for (int c = 0; c < NCHUNK; c++) {
        CP_WAIT1();                            // chunk c landed (c+1 in flight)
        __syncthreads();                       // all warps finished consuming chunk c-1

        if (c + 2 < NCHUNK)
            stage_chunk(c + 2, (bc == 0) ? 2 : bc - 1, sbase, idx_s, cx, tid);
        CP_COMMIT();                           // keep group numbering stable

        const char* stp = smem + OFF_STAGE + bc * STAGE_B;
        const uint32_t stu = sbase + OFF_STAGE + (uint32_t)bc * STAGE_B;
        const bool has_sim = (c < 16);

#pragma unroll
        for (int h32 = 0; h32 < 2; h32++) {    // two 32-k halves per chunk
            if (!has_sim && h32 == 1 && false) {}
            // B'' fold in registers: bpp[nf] = {b0s0, b1s0, b0s1, b1s1} half2s
            uint32_t bpp[4][4];
            {
                uint4 am4 = make_uint4(0, 0, 0, 0);
                if (has_sim) am4 = *(const uint4*)(stp + ST_AM + mi * 128 + h32 * 64 + t * 16);
#pragma unroll
                for (int nf = 0; nf < 4; nf++) {
                    int n = nb + nf * 8 + q;
                    uint4 wb = *(const uint4*)(stp + ST_WB + n * 128 + h32 * 64 + t * 16);
                    if (has_sim) {
                        uint4 ws = *(const uint4*)(stp + ST_WS + n * 128 + h32 * 64 + t * 16);
                        bpp[nf][0] = hfma2u(am4.x, ws.x, wb.x);
                        bpp[nf][1] = hfma2u(am4.y, ws.y, wb.y);
                        bpp[nf][2] = hfma2u(am4.z, ws.z, wb.z);
                        bpp[nf][3] = hfma2u(am4.w, ws.w, wb.w);
                    } else {
                        bpp[nf][0] = wb.x; bpp[nf][1] = wb.y;
                        bpp[nf][2] = wb.z; bpp[nf][3] = wb.w;
                    }
                }
            }
#pragma unroll
            for (int s = 0; s < 2; s++) {      // two k16 steps per half
                uint32_t a_[4][4];
#pragma unroll
                for (int i = 0; i < 4; i++)
                    LDSM_X4(a_[i][0], a_[i][1], a_[i][2], a_[i][3],
                            stu + a_lane_off + (uint32_t)(i * 16 * 144 + h32 * 64 + s * 32));
#pragma unroll
                for (int nf = 0; nf < 4; nf++) {
                    uint32_t b0r = bpp[nf][2 * s], b1r = bpp[nf][2 * s + 1];
#pragma unroll
                    for (int i = 0; i < 4; i++)
                        mma_f16(acc[i][nf], a_[i][0], a_[i][1], a_[i][2], a_[i][3], b0r, b1r);
                }
            }
        }
        bc = (bc == 2) ? 0 : bc + 1;
    }

    // ---- epilogue ----
    aproj_s[tid] = g_Aproj[(size_t)(b0 + (tid >> 7)) * HID + (tid & 127)];
    __syncthreads();                            // aproj visible + stage buffers reusable

    float* part = (float*)(smem + OFF_STAGE);   // [256][4] score partials
    const float  bo  = __ldg(b_out);
    const float* apq = aproj_s + mi * 128;
#pragma unroll
    for (int i = 0; i < 4; i++) {
        float s0 = 0.f, s1 = 0.f;               // rows rb+16i+q, rb+16i+q+8
#pragma unroll
        for (int nf = 0; nf < 4; nf++) {
            int n0 = nb + nf * 8 + 2 * t, n1 = n0 + 1;
            float w0 = wout_s[n0], w1 = wout_s[n1];
            float ap0 = apq[n0], ap1 = apq[n1];
            float h;
            h = acc[i][nf][0] + ap0; h = fmaxf(h, 0.f) + 0.01f * fminf(h, 0.f); s0 += h * w0;
            h = acc[i][nf][1] + ap1; h = fmaxf(h, 0.f) + 0.01f * fminf(h, 0.f); s0 += h * w1;
            h = acc[i][nf][2] + ap0; h = fmaxf(h, 0.f) + 0.01f * fminf(h, 0.f); s1 += h * w0;
            h = acc[i][nf][3] + ap1; h = fmaxf(h, 0.f) + 0.01f * fminf(h, 0.f); s1 += h * w1;
        }
        s0 += __shfl_xor_sync(0xffffffffu, s0, 1);
        s0 += __shfl_xor_sync(0xffffffffu, s0, 2);
        s1 += __shfl_xor_sync(0xffffffffu, s1, 1);
        s1 += __shfl_xor_sync(0xffffffffu, s1, 2);
        if (t == 0) {
            part[(rb + 16 * i + q) * 4 + nh]     = s0;
            part[(rb + 16 * i + q + 8) * 4 + nh] = s1;
        }
    }
    __syncthreads();

    if (tid < 256) {
        float sc = part[tid * 4] + part[tid * 4 + 1] + part[tid * 4 + 2] + part[tid * 4 + 3];
        int a = tid & 63, bg = b0 + (tid >> 6);
        if (a < n_ants)
            out[(size_t)bg * (n_ants + 1) + 1 + a] =
                rough[(size_t)bg * n_ants + a] + bo + sc;
        if (a == 0) out[(size_t)bg * (n_ants + 1)] = EPSV;
    }
}

// -------------------- launch --------------------
extern "C" void kernel_launch(void* const* d_in, const int* in_sizes, int n_in,
                              void* d_out, int out_size) {
    const float* all_m = (const float*)d_in[0];
    const float* m_b   = (const float*)d_in[1];
    const float* pw    = (const float*)d_in[2];
    const void*  idx   = d_in[3];
    const float* rough = (const float*)d_in[4];
    const float* W1    = (const float*)d_in[5];
    const float* b1    = (const float*)d_in[6];
    const float* Wo    = (const float*)d_in[7];
    const float* bo    = (const float*)d_in[8];
    float* out = (float*)d_out;

    const int n_mentions = in_sizes[0] / EMB;  // 10000
    const int batch      = in_sizes[1] / EMB;  // 512
    const int n_ants     = in_sizes[3] / batch;// 50

    cudaFuncSetAttribute(pair_mma_kernel,
                         cudaFuncAttributeMaxDynamicSharedMemorySize, SMEM_TOTAL);

    prep_kernel<<<PREP_MAIN_BLKS + APROJ_BLKS, 256>>>(all_m, m_b, pw, W1, b1,
                                                      (const unsigned*)idx, in_sizes[3],
                                                      n_mentions, batch, n_ants);
    pair_mma_kernel<<<batch / 4, 512, SMEM_TOTAL>>>(idx, rough, Wo, bo, out, n_ants);
}

// round 15
// speedup vs baseline: 1.4126x; 1.1900x over previous
#include <cuda_runtime.h>
#include <cuda_fp16.h>
#include <cstdint>

#define EMB    1024
#define HID    128
#define PW     64
#define KSEG   2112          // W1 rows [1024,3136): bm(1024) + sim(1024) + pw(64)
#define NCHUNK 17            // 16 e-chunks (K=64, sim folded into B) + 1 pw chunk (K=64)
#define EPSV   1e-7f
#define APROJ_BLKS     128
#define PREP_MAIN_BLKS 1184

// -------------------- device scratch (no allocs allowed) --------------------
__device__ __half g_allm_h[10016 * EMB];   // fp16 all_mentions, plain layout
__device__ __half g_W1Th[HID * KSEG];      // fp16 W1^T, per-32-chunk fragment-permuted
__device__ __half g_amb_hp[512 * EMB];     // fp16 mentions_batch, fragment-permuted
__device__ __half g_pw_h[512 * 64 * PW];   // fp16 pw, plain
__device__ float  g_Aproj[512 * HID];      // fp32 m_b @ W1[0:1024] + b1
__device__ int    g_idx64;

// fragment permutation within a 32-k chunk (matches m16n8k16 B/mult layout):
// t=(k>>1)&3, hi=(k>>3)&1, b=k&1, h16=k>>4  ->  pos = t*8 + h16*4 + hi*2 + b
__device__ __forceinline__ int permk(int kk) {
    return ((kk >> 1) & 3) * 8 + (kk >> 4) * 4 + ((kk >> 3) & 1) * 2 + (kk & 1);
}

// -------------------- helpers --------------------
__device__ __forceinline__ uint32_t smem_u32(const void* p) {
    uint32_t a;
    asm("{ .reg .u64 t; cvta.to.shared.u64 t, %1; cvt.u32.u64 %0, t; }" : "=r"(a) : "l"(p));
    return a;
}
__device__ __forceinline__ unsigned long long to_global(const void* p) {
    unsigned long long g;
    asm("cvta.to.global.u64 %0, %1;" : "=l"(g) : "l"(p));
    return g;
}
#define CP16(dst_s32, src_g64) \
    asm volatile("cp.async.cg.shared.global [%0], [%1], 16;" :: "r"(dst_s32), "l"(src_g64) : "memory")
#define CP_COMMIT() asm volatile("cp.async.commit_group;" ::: "memory")
#define CP_WAIT1()  asm volatile("cp.async.wait_group 1;" ::: "memory")

__device__ __forceinline__ void mma_f16(float c[4], uint32_t a0, uint32_t a1, uint32_t a2, uint32_t a3,
                                        uint32_t b0, uint32_t b1) {
    asm volatile("mma.sync.aligned.m16n8k16.row.col.f32.f16.f16.f32 "
                 "{%0,%1,%2,%3}, {%4,%5,%6,%7}, {%8,%9}, {%0,%1,%2,%3};"
                 : "+f"(c[0]), "+f"(c[1]), "+f"(c[2]), "+f"(c[3])
                 : "r"(a0), "r"(a1), "r"(a2), "r"(a3), "r"(b0), "r"(b1));
}
#define LDSM_X4(r0, r1, r2, r3, addr) \
    asm volatile("ldmatrix.sync.aligned.m8n8.x4.shared.b16 {%0,%1,%2,%3}, [%4];" \
                 : "=r"(r0), "=r"(r1), "=r"(r2), "=r"(r3) : "r"(addr))

__device__ __forceinline__ uint32_t hfma2u(uint32_t a, uint32_t b, uint32_t c) {
    uint32_t d;
    asm("fma.rn.f16x2 %0, %1, %2, %3;" : "=r"(d) : "r"(a), "r"(b), "r"(c));
    return d;
}
__device__ __forceinline__ int load_idx(const void* p, size_t pos, int is64) {
    return is64 ? (int)((const long long*)p)[pos] : ((const int*)p)[pos];
}

// -------------------- prep kernel --------------------
// Blocks [0, APROJ_BLKS): block bi -> g_Aproj rows [4bi, 4bi+4), exact fp32, wide MLP.
// Blocks [APROJ_BLKS, APROJ_BLKS+PREP_MAIN_BLKS): grid-stride fp16 conversions + idx detect.
__global__ __launch_bounds__(256)
void prep_kernel(const float* __restrict__ all_m, const float* __restrict__ m_b,
                 const float* __restrict__ pw, const float* __restrict__ W1,
                 const float* __restrict__ b1,
                 const unsigned* __restrict__ idxw, int n_words,
                 int n_mentions, int batch, int n_ants) {
    const int tid = threadIdx.x;
    if (blockIdx.x < APROJ_BLKS) {
        // ---- Aproj: thread = (ks = tid>>5 in 0..7, n4 = tid&31); 128 coalesced LDG.128 ----
        __shared__ float  mbs[4 * EMB];          // 16 KB
        __shared__ float4 red[8 * 32 * 4];       // [ks][n4][row] = 16 KB
        const int r0 = blockIdx.x * 4;
        for (int i = tid; i < EMB; i += 256)
            ((float4*)mbs)[i] = ((const float4*)(m_b + (size_t)r0 * EMB))[i];
        __syncthreads();
        const int ks = tid >> 5, n4 = tid & 31;
        float4 a0 = {0,0,0,0}, a1 = {0,0,0,0}, a2 = {0,0,0,0}, a3 = {0,0,0,0};
        const float4* wp = (const float4*)W1 + n4;
#pragma unroll 4
        for (int k = ks * 128; k < ks * 128 + 128; k++) {
            float4 w = __ldg(wp + (size_t)k * 32);
            float m0 = mbs[k], m1 = mbs[EMB + k], m2 = mbs[2 * EMB + k], m3 = mbs[3 * EMB + k];
            a0.x += m0 * w.x; a0.y += m0 * w.y; a0.z += m0 * w.z; a0.w += m0 * w.w;
            a1.x += m1 * w.x; a1.y += m1 * w.y; a1.z += m1 * w.z; a1.w += m1 * w.w;
            a2.x += m2 * w.x; a2.y += m2 * w.y; a2.z += m2 * w.z; a2.w += m2 * w.w;
            a3.x += m3 * w.x; a3.y += m3 * w.y; a3.z += m3 * w.z; a3.w += m3 * w.w;
        }
        red[(ks * 32 + n4) * 4 + 0] = a0;
        red[(ks * 32 + n4) * 4 + 1] = a1;
        red[(ks * 32 + n4) * 4 + 2] = a2;
        red[(ks * 32 + n4) * 4 + 3] = a3;
        __syncthreads();
        if (tid < 128) {                          // thread -> output column n = tid
            const int n = tid, nn4 = n >> 2, cc = n & 3;
            float bb = b1[n];
#pragma unroll
            for (int j = 0; j < 4; j++) {
                float s = bb;
#pragma unroll
                for (int k8 = 0; k8 < 8; k8++) {
                    float4 v = red[(k8 * 32 + nn4) * 4 + j];
                    s += cc == 0 ? v.x : cc == 1 ? v.y : cc == 2 ? v.z : v.w;
                }
                g_Aproj[(size_t)(r0 + j) * HID + n] = s;
            }
        }
        return;
    }
    const int cb = blockIdx.x - APROJ_BLKS;
    if (cb == 0 && tid == 0) {
        unsigned acc = 0;
        int m = n_words < 256 ? n_words : 256;
        for (int i = 1; i < m; i += 2) acc |= idxw[i];
        g_idx64 = (acc == 0u) ? 1 : 0;
    }
    const long long n4a = (long long)n_mentions * EMB / 4;
    const long long nw1 = (long long)KSEG * HID;
    const long long nmb = (long long)batch * EMB;
    const long long npw = (long long)batch * n_ants * PW;
    const long long TOT = n4a + nw1 + nmb + npw;
    const long long stride = (long long)PREP_MAIN_BLKS * 256;
    for (long long i = (long long)cb * 256 + tid; i < TOT; i += stride) {
        if (i < n4a) {
            float4 v = ((const float4*)all_m)[i];
            __half2* d = (__half2*)(g_allm_h + i * 4);
            d[0] = __floats2half2_rn(v.x, v.y);
            d[1] = __floats2half2_rn(v.z, v.w);
        } else if (i < n4a + nw1) {
            long long j = i - n4a;
            int k = (int)(j / HID), n = (int)(j % HID);
            float v = W1[(size_t)(1024 + k) * HID + n];
            g_W1Th[(size_t)n * KSEG + (k & ~31) + permk(k & 31)] = __float2half_rn(v);
        } else if (i < n4a + nw1 + nmb) {
            long long j = i - n4a - nw1;
            int b = (int)(j >> 10), k = (int)(j & 1023);
            g_amb_hp[(size_t)b * EMB + (k & ~31) + permk(k & 31)] = __float2half_rn(m_b[j]);
        } else {
            long long j = i - n4a - nw1 - nmb;
            g_pw_h[j] = __float2half_rn(pw[j]);
        }
    }
}

// -------------------- fused fp16 pair kernel --------------------
// Block: 4 batch rows -> M=256, N=128, 512 threads / 16 warps, grid = batch/4 = 128.
// Warp (mi = wid&3, nh = wid>>2): rows [64mi,64mi+64), cols [32nh,32nh+32); bq == mi.
// K=64 chunks; 3-stage cp.async pipeline, one barrier per chunk.
// W rows bank-swizzled: 16B unit at offset ^= ((n&1)<<6) -> conflict-free fold LDS.128.
#define OFF_IDX    0                     // 256 ints
#define OFF_WOUT   1024                  // 128 f
#define OFF_APROJ  1536                  // 512 f
#define OFF_STAGE  4096
#define ST_A       0                     // 256 rows x 144 B (64 halfs + 16B pad)
#define ST_AM      36864                 // 4 rows x 128 B (two permuted 32-k halves)
#define ST_WB      37376                 // 128 n x 128 B, XOR-swizzled
#define ST_WS      53760                 // 128 n x 128 B, XOR-swizzled
#define STAGE_B    70144
#define SMEM_TOTAL (OFF_STAGE + 3 * STAGE_B)   // 214528

struct StageCtx {
    unsigned long long allm_g, w1t_g, pw_g, amb_g;
    int b0, n_ants;
};

__device__ __forceinline__ void stage_chunk(int c, int buf, uint32_t sbase,
                                            const int* idx_s, const StageCtx& cx, int tid) {
    const uint32_t stg = sbase + OFF_STAGE + (uint32_t)buf * STAGE_B;
    if (c < 16) {
        const int ec = c * 64;
#pragma unroll
        for (int it = 0; it < 4; it++) {       // A: gathered bm rows [256][64] fp16
            int id = tid + it * 512;
            int r = id >> 3, f8 = id & 7;
            unsigned long long src = cx.allm_g + ((size_t)idx_s[r] * EMB + ec) * 2ull + f8 * 16;
            CP16(stg + ST_A + (uint32_t)(r * 144 + f8 * 16), src);
        }
#pragma unroll
        for (int it = 0; it < 4; it++) {       // WB / WS (permuted fp16, XOR-swizzled dst)
            int id = tid + it * 512;
            int seg = id >> 10, n = (id >> 3) & 127, f8 = id & 7;
            unsigned long long src = cx.w1t_g +
                ((size_t)n * KSEG + (seg ? 1024 + ec : ec)) * 2ull + f8 * 16;
            uint32_t dst = (uint32_t)(n * 128 + ((f8 * 16) ^ ((n & 1) << 6)));
            CP16(stg + (seg ? ST_WS : ST_WB) + dst, src);
        }
        if (tid < 32) {                        // AM: permuted am chunk [4][64] fp16 (no swizzle)
            int q = tid >> 3, f8 = tid & 7;
            unsigned long long src = cx.amb_g + ((size_t)(cx.b0 + q) * EMB + ec) * 2ull + f8 * 16;
            CP16(stg + ST_AM + (uint32_t)(q * 128 + f8 * 16), src);
        }
    } else {
        // pw chunk: K = 64 = full PW
#pragma unroll
        for (int it = 0; it < 4; it++) {       // A: pw values [256][64] fp16
            int id = tid + it * 512;
            int r = id >> 3, f8 = id & 7;
            int bq = r >> 6, a = r & 63; if (a >= cx.n_ants) a = cx.n_ants - 1;
            unsigned long long src = cx.pw_g +
                ((size_t)(cx.b0 + bq) * cx.n_ants + a) * PW * 2ull + f8 * 16;
            CP16(stg + ST_A + (uint32_t)(r * 144 + f8 * 16), src);
        }
#pragma unroll
        for (int it = 0; it < 2; it++) {       // B: W1p (permuted, swizzled) into WB region
            int id = tid + it * 512;
            int n = id >> 3, f8 = id & 7;
            unsigned long long src = cx.w1t_g + ((size_t)n * KSEG + 2048) * 2ull + f8 * 16;
            uint32_t dst = (uint32_t)(n * 128 + ((f8 * 16) ^ ((n & 1) << 6)));
            CP16(stg + ST_WB + dst, src);
        }
    }
}

__global__ __launch_bounds__(512, 1)
void pair_mma_kernel(const void*  __restrict__ top_idx,
                     const float* __restrict__ rough,
                     const float* __restrict__ W_out,
                     const float* __restrict__ b_out,
                     float* __restrict__ out,
                     int n_ants) {
    extern __shared__ char smem[];
    const uint32_t sbase = smem_u32(smem);
    const int tid  = threadIdx.x;
    const int lane = tid & 31;
    const int wid  = tid >> 5;
    const int t    = lane & 3;       // k lane within quad
    const int q    = lane >> 2;      // row/col lane (0..7)
    const int b0   = blockIdx.x * 4;
    const int mi   = wid & 3;        // m-tile: rows [64mi,64mi+64); == bq
    const int nh   = wid >> 2;       // n-quarter: cols [32nh,32nh+32)
    const int rb   = mi * 64, nb = nh * 32;

    int*   idx_s   = (int*)(smem + OFF_IDX);
    float* wout_s  = (float*)(smem + OFF_WOUT);
    float* aproj_s = (float*)(smem + OFF_APROJ);

    StageCtx cx;
    cx.allm_g = to_global(g_allm_h);
    cx.w1t_g  = to_global(g_W1Th);
    cx.pw_g   = to_global(g_pw_h);
    cx.amb_g  = to_global(g_amb_hp);
    cx.b0 = b0; cx.n_ants = n_ants;

    if (tid < 256) {
        int a = tid & 63; if (a >= n_ants) a = n_ants - 1;
        idx_s[tid] = load_idx(top_idx, (size_t)(b0 + (tid >> 6)) * n_ants + a, g_idx64);
    }
    if (tid < 128) wout_s[tid] = W_out[tid];
    __syncthreads();

    stage_chunk(0, 0, sbase, idx_s, cx, tid); CP_COMMIT();
    stage_chunk(1, 1, sbase, idx_s, cx, tid); CP_COMMIT();

    // accumulators: 4 m-frags x 4 n-frags x 4 (fp32)
    float acc[4][4][4];
#pragma unroll
    for (int i = 0; i < 4; i++)
#pragma unroll
        for (int nf = 0; nf < 4; nf++)
#pragma unroll
            for (int r = 0; r < 4; r++) acc[i][nf][r] = 0.f;

    // ldmatrix lane base: row rb + (lane&15), k-half (lane>>4); 144B pitch is conflict-free
    const uint32_t a_lane_off = (uint32_t)((rb + (lane & 15)) * 144 + (lane >> 4) * 16);

    int bc = 0;                                // consume buffer = c % 3
    for (int c = 0; c < NCHUNK; c++) {
        CP_WAIT1();                            // chunk c landed (c+1 in flight)
        __syncthreads();                       // all warps finished consuming chunk c-1

        if (c + 2 < NCHUNK)
            stage_chunk(c + 2, (bc == 0) ? 2 : bc - 1, sbase, idx_s, cx, tid);
        CP_COMMIT();                           // keep group numbering stable

        const char* stp = smem + OFF_STAGE + bc * STAGE_B;
        const uint32_t stu = sbase + OFF_STAGE + (uint32_t)bc * STAGE_B;
        const bool has_sim = (c < 16);

#pragma unroll
        for (int h32 = 0; h32 < 2; h32++) {    // two 32-k halves per chunk
            // B'' fold in registers; swizzled W reads (conflict-free)
            uint32_t bpp[4][4];
            {
                uint4 am4 = make_uint4(0, 0, 0, 0);
                if (has_sim) am4 = *(const uint4*)(stp + ST_AM + mi * 128 + h32 * 64 + t * 16);
#pragma unroll
                for (int nf = 0; nf < 4; nf++) {
                    int n = nb + nf * 8 + q;
                    uint32_t woff = (uint32_t)(n * 128 + ((h32 * 64 + t * 16) ^ ((n & 1) << 6)));
                    uint4 wb = *(const uint4*)(stp + ST_WB + woff);
                    if (has_sim) {
                        uint4 ws = *(const uint4*)(stp + ST_WS + woff);
                        bpp[nf][0] = hfma2u(am4.x, ws.x, wb.x);
                        bpp[nf][1] = hfma2u(am4.y, ws.y, wb.y);
                        bpp[nf][2] = hfma2u(am4.z, ws.z, wb.z);
                        bpp[nf][3] = hfma2u(am4.w, ws.w, wb.w);
                    } else {
                        bpp[nf][0] = wb.x; bpp[nf][1] = wb.y;
                        bpp[nf][2] = wb.z; bpp[nf][3] = wb.w;
                    }
                }
            }
#pragma unroll
            for (int s = 0; s < 2; s++) {      // two k16 steps per half
                uint32_t a_[4][4];
#pragma unroll
                for (int i = 0; i < 4; i++)
                    LDSM_X4(a_[i][0], a_[i][1], a_[i][2], a_[i][3],
                            stu + a_lane_off + (uint32_t)(i * 16 * 144 + h32 * 64 + s * 32));
#pragma unroll
                for (int nf = 0; nf < 4; nf++) {
                    uint32_t b0r = bpp[nf][2 * s], b1r = bpp[nf][2 * s + 1];
#pragma unroll
                    for (int i = 0; i < 4; i++)
                        mma_f16(acc[i][nf], a_[i][0], a_[i][1], a_[i][2], a_[i][3], b0r, b1r);
                }
            }
        }
        bc = (bc == 2) ? 0 : bc + 1;
    }

    // ---- epilogue ----
    aproj_s[tid] = g_Aproj[(size_t)(b0 + (tid >> 7)) * HID + (tid & 127)];
    __syncthreads();                            // aproj visible + stage buffers reusable

    float* part = (float*)(smem + OFF_STAGE);   // [256][4] score partials
    const float  bo  = __ldg(b_out);
    const float* apq = aproj_s + mi * 128;
#pragma unroll
    for (int i = 0; i < 4; i++) {
        float s0 = 0.f, s1 = 0.f;               // rows rb+16i+q, rb+16i+q+8
#pragma unroll
        for (int nf = 0; nf < 4; nf++) {
            int n0 = nb + nf * 8 + 2 * t, n1 = n0 + 1;
            float w0 = wout_s[n0], w1 = wout_s[n1];
            float ap0 = apq[n0], ap1 = apq[n1];
            float h;
            h = acc[i][nf][0] + ap0; h = fmaxf(h, 0.f) + 0.01f * fminf(h, 0.f); s0 += h * w0;
            h = acc[i][nf][1] + ap1; h = fmaxf(h, 0.f) + 0.01f * fminf(h, 0.f); s0 += h * w1;
            h = acc[i][nf][2] + ap0; h = fmaxf(h, 0.f) + 0.01f * fminf(h, 0.f); s1 += h * w0;
            h = acc[i][nf][3] + ap1; h = fmaxf(h, 0.f) + 0.01f * fminf(h, 0.f); s1 += h * w1;
        }
        s0 += __shfl_xor_sync(0xffffffffu, s0, 1);
        s0 += __shfl_xor_sync(0xffffffffu, s0, 2);
        s1 += __shfl_xor_sync(0xffffffffu, s1, 1);
        s1 += __shfl_xor_sync(0xffffffffu, s1, 2);
        if (t == 0) {
            part[(rb + 16 * i + q) * 4 + nh]     = s0;
            part[(rb + 16 * i + q + 8) * 4 + nh] = s1;
        }
    }
    __syncthreads();

    if (tid < 256) {
        float sc = part[tid * 4] + part[tid * 4 + 1] + part[tid * 4 + 2] + part[tid * 4 + 3];
        int a = tid & 63, bg = b0 + (tid >> 6);
        if (a < n_ants)
            out[(size_t)bg * (n_ants + 1) + 1 + a] =
                rough[(size_t)bg * n_ants + a] + bo + sc;
        if (a == 0) out[(size_t)bg * (n_ants + 1)] = EPSV;
    }
}

// -------------------- launch --------------------
extern "C" void kernel_launch(void* const* d_in, const int* in_sizes, int n_in,
                              void* d_out, int out_size) {
    const float* all_m = (const float*)d_in[0];
    const float* m_b   = (const float*)d_in[1];
    const float* pw    = (const float*)d_in[2];
    const void*  idx   = d_in[3];
    const float* rough = (const float*)d_in[4];
    const float* W1    = (const float*)d_in[5];
    const float* b1    = (const float*)d_in[6];
    const float* Wo    = (const float*)d_in[7];
    const float* bo    = (const float*)d_in[8];
    float* out = (float*)d_out;

    const int n_mentions = in_sizes[0] / EMB;  // 10000
    const int batch      = in_sizes[1] / EMB;  // 512
    const int n_ants     = in_sizes[3] / batch;// 50

    cudaFuncSetAttribute(pair_mma_kernel,
                         cudaFuncAttributeMaxDynamicSharedMemorySize, SMEM_TOTAL);

    prep_kernel<<<APROJ_BLKS + PREP_MAIN_BLKS, 256>>>(all_m, m_b, pw, W1, b1,
                                                      (const unsigned*)idx, in_sizes[3],
                                                      n_mentions, batch, n_ants);
    pair_mma_kernel<<<batch / 4, 512, SMEM_TOTAL>>>(idx, rough, Wo, bo, out, n_ants);
}